// round 7
// baseline (speedup 1.0000x reference)
#include <cuda_runtime.h>
#include <cuda_bf16.h>
#include <cstdint>
#include <math.h>

#define S 2048
#define D 2048
#define H 16
#define HD 128

// ---- scratch (allocation-free rule: __device__ globals) ----
__device__ float g_q[H * S * HD];
__device__ float g_k[H * S * HD];
__device__ float g_v[H * S * HD];
__device__ __nv_bfloat16 g_hs_hi[S * D], g_hs_lo[S * D];
__device__ __nv_bfloat16 g_w_hi[4][D * D], g_w_lo[4][D * D];
__device__ __nv_bfloat16 g_o_hi[S * D], g_o_lo[S * D];
__device__ __nv_bfloat16 g_qh[H * S * HD], g_ql[H * S * HD];
__device__ __nv_bfloat16 g_kh[H * S * HD], g_kl[H * S * HD];
__device__ __nv_bfloat16 g_vh[H * S * HD], g_vl[H * S * HD];

// ============================================================
// helpers (arch-agnostic: mma.sync / ldmatrix / cp.async)
// ============================================================
__device__ __forceinline__ uint32_t smem_u32(const void* p) {
    uint32_t a;
    asm("{ .reg .u64 t; cvta.to.shared.u64 t, %1; cvt.u32.u64 %0, t; }"
        : "=r"(a) : "l"(p));
    return a;
}
__device__ __forceinline__ void mma16816(float* c, const uint32_t* a,
                                         const uint32_t* b) {
    asm volatile(
        "mma.sync.aligned.m16n8k16.row.col.f32.bf16.bf16.f32 "
        "{%0,%1,%2,%3}, {%4,%5,%6,%7}, {%8,%9}, {%0,%1,%2,%3};"
        : "+f"(c[0]), "+f"(c[1]), "+f"(c[2]), "+f"(c[3])
        : "r"(a[0]), "r"(a[1]), "r"(a[2]), "r"(a[3]), "r"(b[0]), "r"(b[1]));
}
__device__ __forceinline__ void ldsm4(uint32_t* r, uint32_t addr) {
    asm volatile("ldmatrix.sync.aligned.m8n8.x4.shared.b16 {%0,%1,%2,%3}, [%4];"
                 : "=r"(r[0]), "=r"(r[1]), "=r"(r[2]), "=r"(r[3]) : "r"(addr));
}
__device__ __forceinline__ void ldsm4t(uint32_t* r, uint32_t addr) {
    asm volatile("ldmatrix.sync.aligned.m8n8.x4.trans.shared.b16 {%0,%1,%2,%3}, [%4];"
                 : "=r"(r[0]), "=r"(r[1]), "=r"(r[2]), "=r"(r[3]) : "r"(addr));
}
#define CPASYNC16(sa, ga) \
    asm volatile("cp.async.cg.shared.global [%0], [%1], 16;" \
                 :: "r"(sa), "l"(ga) : "memory")
#define CP_COMMIT() asm volatile("cp.async.commit_group;" ::: "memory")
#define CP_WAIT(N)  asm volatile("cp.async.wait_group %0;" :: "n"(N) : "memory")

__device__ __forceinline__ uint32_t pk2(float a, float b) {
    __nv_bfloat162 t = __floats2bfloat162_rn(a, b);
    return *(uint32_t*)&t;
}

// ============================================================
// fp32 -> (hi, lo) bf16 split
// ============================================================
__global__ __launch_bounds__(256) void split_kernel(
    const float* __restrict__ x, __nv_bfloat16* __restrict__ hi,
    __nv_bfloat16* __restrict__ lo, int n)
{
    int i = (blockIdx.x * 256 + threadIdx.x) * 4;
    if (i >= n) return;
    float4 v = *(const float4*)(x + i);
    float f[4] = {v.x, v.y, v.z, v.w};
    __nv_bfloat16 hb[4], lb[4];
#pragma unroll
    for (int j = 0; j < 4; j++) {
        hb[j] = __float2bfloat16(f[j]);
        lb[j] = __float2bfloat16(f[j] - __bfloat162float(hb[j]));
    }
    ((__nv_bfloat162*)(hi + i))[0] = __nv_bfloat162(hb[0], hb[1]);
    ((__nv_bfloat162*)(hi + i))[1] = __nv_bfloat162(hb[2], hb[3]);
    ((__nv_bfloat162*)(lo + i))[0] = __nv_bfloat162(lb[0], lb[1]);
    ((__nv_bfloat162*)(lo + i))[1] = __nv_bfloat162(lb[2], lb[3]);
}

// ============================================================
// mma.sync split-bf16 GEMM: C = A @ B^T, M=N=K=2048.
// CTA tile 256x128 (512 thr, 16 warps), K-stage 32, 3-stage
// cp.async pipeline, pitch 80B. Grid = 128 CTAs = one wave.
// headmode=1: C[((n>>7)*2048 + m)*128 + (n&127)], else C[m*2048+n].
// ============================================================
#define PITCH 80
#define AMAT (256 * PITCH)           // 20480
#define BMAT (128 * PITCH)           // 10240
#define STAGESZ (2 * AMAT + 2 * BMAT) // 61440
#define GSMEM (3 * STAGESZ)          // 184320

__global__ __launch_bounds__(512, 1) void gemm_mma_kernel(
    const __nv_bfloat16* __restrict__ Ahi, const __nv_bfloat16* __restrict__ Alo,
    const __nv_bfloat16* __restrict__ Bhi, const __nv_bfloat16* __restrict__ Blo,
    float* __restrict__ C, int headmode)
{
    extern __shared__ char smem[];
    const uint32_t sb = smem_u32(smem);
    const int t = threadIdx.x;
    const int lane = t & 31;
    const int w = t >> 5;
    const int mw = (w >> 1) * 32;      // 0..224
    const int nw = (w & 1) * 64;
    const int mbase = blockIdx.y * 256;
    const int nbase = blockIdx.x * 128;

    const __nv_bfloat16* pAh = Ahi + (size_t)mbase * 2048;
    const __nv_bfloat16* pAl = Alo + (size_t)mbase * 2048;
    const __nv_bfloat16* pBh = Bhi + (size_t)nbase * 2048;
    const __nv_bfloat16* pBl = Blo + (size_t)nbase * 2048;

    float acc[2][8][4];
#pragma unroll
    for (int i = 0; i < 2; i++)
#pragma unroll
        for (int j = 0; j < 8; j++)
#pragma unroll
            for (int k = 0; k < 4; k++) acc[i][j][k] = 0.f;

    // stage: A 256 rows x 32 bf16 (64B), B 128 rows x 32 bf16; pitch 80
#define LOAD_STAGE(sidx, k0) do {                                            \
        uint32_t base = sb + ((sidx) % 3) * STAGESZ;                         \
        _Pragma("unroll")                                                    \
        for (int r = 0; r < 2; r++) {                                        \
            int idx = t + 512 * r;                                           \
            int row = idx >> 2, c = idx & 3;                                 \
            size_t go = (size_t)row * 2048 + (k0) + c * 8;                   \
            uint32_t so = row * PITCH + c * 16;                              \
            CPASYNC16(base + so,        pAh + go);                           \
            CPASYNC16(base + AMAT + so, pAl + go);                           \
        }                                                                    \
        {                                                                    \
            int row = t >> 2, c = t & 3;                                     \
            size_t go = (size_t)row * 2048 + (k0) + c * 8;                   \
            uint32_t so = row * PITCH + c * 16;                              \
            CPASYNC16(base + 2 * AMAT + so,        pBh + go);                \
            CPASYNC16(base + 2 * AMAT + BMAT + so, pBl + go);                \
        }                                                                    \
        CP_COMMIT();                                                         \
    } while (0)

    LOAD_STAGE(0, 0);
    LOAD_STAGE(1, 32);

    for (int s = 0; s < 64; s++) {
        if (s < 62)      { LOAD_STAGE(s + 2, (s + 2) * 32); CP_WAIT(2); }
        else if (s == 62){ CP_WAIT(1); }
        else             { CP_WAIT(0); }
        __syncthreads();
        const uint32_t base = sb + (s % 3) * STAGESZ;
        const uint32_t aHiB = base;
        const uint32_t aLoB = base + AMAT;
        const uint32_t bHiB = base + 2 * AMAT;
        const uint32_t bLoB = base + 2 * AMAT + BMAT;
#pragma unroll
        for (int ks = 0; ks < 2; ks++) {
            uint32_t a_hi[2][4], a_lo[2][4];
#pragma unroll
            for (int mt = 0; mt < 2; mt++) {
                int row = mw + mt * 16 + (lane & 15);
                int chunk = 2 * ks + (lane >> 4);
                uint32_t off = row * PITCH + chunk * 16;
                ldsm4(a_hi[mt], aHiB + off);
                ldsm4(a_lo[mt], aLoB + off);
            }
#pragma unroll
            for (int jh = 0; jh < 2; jh++) {
                uint32_t b_hi[4][2], b_lo[4][2];
#pragma unroll
                for (int jj = 0; jj < 2; jj++) {
                    int j = jh * 2 + jj;
                    int row = nw + j * 16 + ((lane >> 4) << 3) + (lane & 7);
                    int chunk = 2 * ks + ((lane >> 3) & 1);
                    uint32_t off = row * PITCH + chunk * 16;
                    uint32_t rh[4], rl[4];
                    ldsm4(rh, bHiB + off);
                    ldsm4(rl, bLoB + off);
                    b_hi[2 * jj][0] = rh[0]; b_hi[2 * jj][1] = rh[1];
                    b_hi[2 * jj + 1][0] = rh[2]; b_hi[2 * jj + 1][1] = rh[3];
                    b_lo[2 * jj][0] = rl[0]; b_lo[2 * jj][1] = rl[1];
                    b_lo[2 * jj + 1][0] = rl[2]; b_lo[2 * jj + 1][1] = rl[3];
                }
                // term-outermost over 8 independent accumulators
#pragma unroll
                for (int mt = 0; mt < 2; mt++)
#pragma unroll
                    for (int nt = 0; nt < 4; nt++)
                        mma16816(acc[mt][jh * 4 + nt], a_hi[mt], b_hi[nt]);
#pragma unroll
                for (int mt = 0; mt < 2; mt++)
#pragma unroll
                    for (int nt = 0; nt < 4; nt++)
                        mma16816(acc[mt][jh * 4 + nt], a_hi[mt], b_lo[nt]);
#pragma unroll
                for (int mt = 0; mt < 2; mt++)
#pragma unroll
                    for (int nt = 0; nt < 4; nt++)
                        mma16816(acc[mt][jh * 4 + nt], a_lo[mt], b_hi[nt]);
            }
        }
        __syncthreads();
    }

#pragma unroll
    for (int mt = 0; mt < 2; mt++)
#pragma unroll
        for (int nt = 0; nt < 8; nt++) {
            const float* a = acc[mt][nt];
            int r0 = mbase + mw + mt * 16 + (lane >> 2);
            int n  = nbase + nw + nt * 8 + 2 * (lane & 3);
            if (headmode) {
                float* p0 = C + ((size_t)(n >> 7) * 2048 + r0) * 128 + (n & 127);
                float* p1 = C + ((size_t)(n >> 7) * 2048 + r0 + 8) * 128 + (n & 127);
                *(float2*)p0 = make_float2(a[0], a[1]);
                *(float2*)p1 = make_float2(a[2], a[3]);
            } else {
                *(float2*)(C + (size_t)r0 * 2048 + n)       = make_float2(a[0], a[1]);
                *(float2*)(C + (size_t)(r0 + 8) * 2048 + n) = make_float2(a[2], a[3]);
            }
        }
}

// ============================================================
// RoPE + IA3 + scale, emitting split bf16 q,k,v.
// ============================================================
__global__ __launch_bounds__(128) void rope_split_kernel(
    const float* __restrict__ Qm, const float* __restrict__ Km,
    const float* __restrict__ Vm,
    const float* __restrict__ cosT, const float* __restrict__ sinT,
    const float* __restrict__ lk, const float* __restrict__ lv,
    __nv_bfloat16* __restrict__ qh, __nv_bfloat16* __restrict__ ql,
    __nv_bfloat16* __restrict__ kh, __nv_bfloat16* __restrict__ kl,
    __nv_bfloat16* __restrict__ vh, __nv_bfloat16* __restrict__ vl)
{
    const int s = blockIdx.x;
    const int h = blockIdx.y;
    const int d = threadIdx.x;
    const float scale = 0.08838834764831845f;   // 1/sqrt(128)
    size_t rb = ((size_t)h * S + s) * HD;
    float c  = cosT[s * HD + d];
    float sn = sinT[s * HD + d];
    int   p  = d ^ 64;
    float sign = (d < 64) ? -1.f : 1.f;
    float q = (Qm[rb + d] * c + sign * Qm[rb + p] * sn) * lk[h * HD + d] * scale;
    float k = Km[rb + d] * c + sign * Km[rb + p] * sn;
    float v = Vm[rb + d] * lv[h * HD + d];
    __nv_bfloat16 qH = __float2bfloat16(q);
    __nv_bfloat16 kH = __float2bfloat16(k);
    __nv_bfloat16 vH = __float2bfloat16(v);
    qh[rb + d] = qH; ql[rb + d] = __float2bfloat16(q - __bfloat162float(qH));
    kh[rb + d] = kH; kl[rb + d] = __float2bfloat16(k - __bfloat162float(kH));
    vh[rb + d] = vH; vl[rb + d] = __float2bfloat16(v - __bfloat162float(vH));
}

// ============================================================
// Causal flash attention, mma.sync split-bf16. (R6, unchanged)
// ============================================================
#define FPB 272
#define QMAT (128 * FPB)
#define KVMAT (64 * FPB)

__global__ __launch_bounds__(256, 1) void flash_mma_kernel(
    const __nv_bfloat16* __restrict__ Qh_, const __nv_bfloat16* __restrict__ Ql_,
    const __nv_bfloat16* __restrict__ Kh_, const __nv_bfloat16* __restrict__ Kl_,
    const __nv_bfloat16* __restrict__ Vh_, const __nv_bfloat16* __restrict__ Vl_,
    __nv_bfloat16* __restrict__ OH, __nv_bfloat16* __restrict__ OL)
{
    extern __shared__ char smem[];
    const uint32_t sb = smem_u32(smem);
    const int t = threadIdx.x, lane = t & 31, w = t >> 5;
    const int qt = 15 - (int)blockIdx.x;
    const int h = blockIdx.y;
    const int mw = w * 16;
    const size_t hoff = (size_t)h * S * HD;
    const __nv_bfloat16* Qhp = Qh_ + hoff + (size_t)qt * 128 * HD;
    const __nv_bfloat16* Qlp = Ql_ + hoff + (size_t)qt * 128 * HD;
    const __nv_bfloat16* Khp = Kh_ + hoff;
    const __nv_bfloat16* Klp = Kl_ + hoff;
    const __nv_bfloat16* Vhp = Vh_ + hoff;
    const __nv_bfloat16* Vlp = Vl_ + hoff;

    const uint32_t qB  = sb;
    const uint32_t kvB = sb + 2 * QMAT;

#pragma unroll
    for (int r = 0; r < 8; r++) {
        int idx = t + 256 * r;
        int row = idx >> 4, c = idx & 15;
        CPASYNC16(qB + row * FPB + c * 16,        Qhp + row * 128 + c * 8);
        CPASYNC16(qB + QMAT + row * FPB + c * 16, Qlp + row * 128 + c * 8);
    }
    CP_COMMIT();

#define LOADKV(kt_, p_) do {                                                  \
        uint32_t b_ = kvB + (p_) * (4 * KVMAT);                               \
        const __nv_bfloat16* g0 = Khp + (size_t)(kt_) * 64 * 128;             \
        const __nv_bfloat16* g1 = Klp + (size_t)(kt_) * 64 * 128;             \
        const __nv_bfloat16* g2 = Vhp + (size_t)(kt_) * 64 * 128;             \
        const __nv_bfloat16* g3 = Vlp + (size_t)(kt_) * 64 * 128;             \
        _Pragma("unroll")                                                     \
        for (int r_ = 0; r_ < 4; r_++) {                                      \
            int idx_ = t + 256 * r_;                                          \
            int row_ = idx_ >> 4, c_ = idx_ & 15;                             \
            uint32_t so_ = row_ * FPB + c_ * 16;                              \
            uint32_t go_ = row_ * 128 + c_ * 8;                               \
            CPASYNC16(b_ + so_,             g0 + go_);                        \
            CPASYNC16(b_ + KVMAT + so_,     g1 + go_);                        \
            CPASYNC16(b_ + 2 * KVMAT + so_, g2 + go_);                        \
            CPASYNC16(b_ + 3 * KVMAT + so_, g3 + go_);                        \
        }                                                                     \
        CP_COMMIT();                                                          \
    } while (0)

    float acc[16][4];
#pragma unroll
    for (int i = 0; i < 16; i++)
#pragma unroll
        for (int j = 0; j < 4; j++) acc[i][j] = 0.f;
    float m0 = -1e30f, m1 = -1e30f, l0 = 0.f, l1 = 0.f;

    const int ktmax = 2 * qt + 1;
    LOADKV(0, 0);

    for (int kt = 0; kt <= ktmax; kt++) {
        if (kt < ktmax) { LOADKV(kt + 1, (kt + 1) & 1); CP_WAIT(1); }
        else            { CP_WAIT(0); }
        __syncthreads();
        const uint32_t base = kvB + (kt & 1) * (4 * KVMAT);

        float s[8][4];
#pragma unroll
        for (int i = 0; i < 8; i++)
#pragma unroll
            for (int j = 0; j < 4; j++) s[i][j] = 0.f;
#pragma unroll
        for (int kc = 0; kc < 8; kc++) {
            uint32_t aH[4], aL[4];
            uint32_t aaddr = qB + (mw + (lane & 15)) * FPB + (2 * kc + (lane >> 4)) * 16;
            ldsm4(aH, aaddr);
            ldsm4(aL, aaddr + QMAT);
            uint32_t bH[8][2], bL[8][2];
#pragma unroll
            for (int j = 0; j < 4; j++) {
                int row = j * 16 + ((lane >> 4) << 3) + (lane & 7);
                uint32_t baddr = base + row * FPB + (2 * kc + ((lane >> 3) & 1)) * 16;
                uint32_t rh[4], rl[4];
                ldsm4(rh, baddr);
                ldsm4(rl, baddr + KVMAT);
                bH[2 * j][0] = rh[0]; bH[2 * j][1] = rh[1];
                bH[2 * j + 1][0] = rh[2]; bH[2 * j + 1][1] = rh[3];
                bL[2 * j][0] = rl[0]; bL[2 * j][1] = rl[1];
                bL[2 * j + 1][0] = rl[2]; bL[2 * j + 1][1] = rl[3];
            }
#pragma unroll
            for (int nb = 0; nb < 8; nb++)
                mma16816(s[nb], aH, bH[nb]);
#pragma unroll
            for (int nb = 0; nb < 8; nb++)
                mma16816(s[nb], aH, bL[nb]);
#pragma unroll
            for (int nb = 0; nb < 8; nb++)
                mma16816(s[nb], aL, bH[nb]);
        }

        const int qrow = qt * 128 + mw + (lane >> 2);
        if (kt * 64 + 63 > qt * 128 + mw) {
#pragma unroll
            for (int nb = 0; nb < 8; nb++) {
                int col = kt * 64 + 8 * nb + 2 * (lane & 3);
                if (col     > qrow)     s[nb][0] = -1e30f;
                if (col + 1 > qrow)     s[nb][1] = -1e30f;
                if (col     > qrow + 8) s[nb][2] = -1e30f;
                if (col + 1 > qrow + 8) s[nb][3] = -1e30f;
            }
        }

        float mx0 = -1e30f, mx1 = -1e30f;
#pragma unroll
        for (int nb = 0; nb < 8; nb++) {
            mx0 = fmaxf(mx0, fmaxf(s[nb][0], s[nb][1]));
            mx1 = fmaxf(mx1, fmaxf(s[nb][2], s[nb][3]));
        }
        mx0 = fmaxf(mx0, __shfl_xor_sync(0xffffffffu, mx0, 1));
        mx0 = fmaxf(mx0, __shfl_xor_sync(0xffffffffu, mx0, 2));
        mx1 = fmaxf(mx1, __shfl_xor_sync(0xffffffffu, mx1, 1));
        mx1 = fmaxf(mx1, __shfl_xor_sync(0xffffffffu, mx1, 2));
        float mn0 = fmaxf(m0, mx0), mn1 = fmaxf(m1, mx1);
        float al0 = __expf(m0 - mn0), al1 = __expf(m1 - mn1);
        m0 = mn0; m1 = mn1;

        float sum0 = 0.f, sum1 = 0.f;
        uint32_t ph0[8], ph1[8], pl0[8], pl1[8];
#pragma unroll
        for (int nb = 0; nb < 8; nb++) {
            float p0 = __expf(s[nb][0] - mn0), p1 = __expf(s[nb][1] - mn0);
            float p2 = __expf(s[nb][2] - mn1), p3 = __expf(s[nb][3] - mn1);
            sum0 += p0 + p1; sum1 += p2 + p3;
            __nv_bfloat162 h01 = __floats2bfloat162_rn(p0, p1);
            __nv_bfloat162 h23 = __floats2bfloat162_rn(p2, p3);
            ph0[nb] = *(uint32_t*)&h01;
            ph1[nb] = *(uint32_t*)&h23;
            pl0[nb] = pk2(p0 - __bfloat162float(h01.x), p1 - __bfloat162float(h01.y));
            pl1[nb] = pk2(p2 - __bfloat162float(h23.x), p3 - __bfloat162float(h23.y));
        }
        sum0 += __shfl_xor_sync(0xffffffffu, sum0, 1);
        sum0 += __shfl_xor_sync(0xffffffffu, sum0, 2);
        sum1 += __shfl_xor_sync(0xffffffffu, sum1, 1);
        sum1 += __shfl_xor_sync(0xffffffffu, sum1, 2);
        l0 = l0 * al0 + sum0;
        l1 = l1 * al1 + sum1;
#pragma unroll
        for (int nb = 0; nb < 16; nb++) {
            acc[nb][0] *= al0; acc[nb][1] *= al0;
            acc[nb][2] *= al1; acc[nb][3] *= al1;
        }

#pragma unroll
        for (int kc = 0; kc < 4; kc++) {
            uint32_t paH[4] = {ph0[2 * kc], ph1[2 * kc], ph0[2 * kc + 1], ph1[2 * kc + 1]};
            uint32_t paL[4] = {pl0[2 * kc], pl1[2 * kc], pl0[2 * kc + 1], pl1[2 * kc + 1]};
#pragma unroll
            for (int nb2 = 0; nb2 < 8; nb2++) {
                uint32_t vaddr = base + 2 * KVMAT +
                                 (kc * 16 + (lane & 15)) * FPB + (2 * nb2 + (lane >> 4)) * 16;
                uint32_t vh[4], vl[4];
                ldsm4t(vh, vaddr);
                ldsm4t(vl, vaddr + KVMAT);
                uint32_t bh0[2] = {vh[0], vh[1]}, bh1[2] = {vh[2], vh[3]};
                uint32_t bl0[2] = {vl[0], vl[1]}, bl1[2] = {vl[2], vl[3]};
                mma16816(acc[2 * nb2], paH, bh0);
                mma16816(acc[2 * nb2 + 1], paH, bh1);
                mma16816(acc[2 * nb2], paH, bl0);
                mma16816(acc[2 * nb2 + 1], paH, bl1);
                mma16816(acc[2 * nb2], paL, bh0);
                mma16816(acc[2 * nb2 + 1], paL, bh1);
            }
        }
        __syncthreads();
    }

    float inv0 = 1.f / l0, inv1 = 1.f / l1;
    int r = qt * 128 + mw + (lane >> 2);
#pragma unroll
    for (int nb = 0; nb < 16; nb++) {
        int col = h * 128 + 8 * nb + 2 * (lane & 3);
        float v0 = acc[nb][0] * inv0, v1 = acc[nb][1] * inv0;
        float v2 = acc[nb][2] * inv1, v3 = acc[nb][3] * inv1;
        __nv_bfloat162 h01 = __floats2bfloat162_rn(v0, v1);
        __nv_bfloat162 h23 = __floats2bfloat162_rn(v2, v3);
        __nv_bfloat162 l01 = __floats2bfloat162_rn(
            v0 - __bfloat162float(h01.x), v1 - __bfloat162float(h01.y));
        __nv_bfloat162 l23 = __floats2bfloat162_rn(
            v2 - __bfloat162float(h23.x), v3 - __bfloat162float(h23.y));
        *(__nv_bfloat162*)&OH[(size_t)r * D + col]       = h01;
        *(__nv_bfloat162*)&OL[(size_t)r * D + col]       = l01;
        *(__nv_bfloat162*)&OH[(size_t)(r + 8) * D + col] = h23;
        *(__nv_bfloat162*)&OL[(size_t)(r + 8) * D + col] = l23;
    }
}

// ============================================================
extern "C" void kernel_launch(void* const* d_in, const int* in_sizes, int n_in,
                              void* d_out, int out_size)
{
    const float* hs   = (const float*)d_in[0];
    const float* cosT = (const float*)d_in[2];
    const float* sinT = (const float*)d_in[3];
    const float* Wq   = (const float*)d_in[4];
    const float* Wk   = (const float*)d_in[5];
    const float* Wv   = (const float*)d_in[6];
    const float* Wo   = (const float*)d_in[7];
    const float* lk   = (const float*)d_in[8];
    const float* lv   = (const float*)d_in[9];
    float* out = (float*)d_out;
    (void)in_sizes; (void)n_in; (void)out_size;

    float *q, *k, *v;
    cudaGetSymbolAddress((void**)&q, g_q);
    cudaGetSymbolAddress((void**)&k, g_k);
    cudaGetSymbolAddress((void**)&v, g_v);
    __nv_bfloat16 *hsH, *hsL, *wH, *wL, *oH, *oL;
    __nv_bfloat16 *qh, *ql, *kh, *kl, *vh, *vl;
    cudaGetSymbolAddress((void**)&hsH, g_hs_hi);
    cudaGetSymbolAddress((void**)&hsL, g_hs_lo);
    cudaGetSymbolAddress((void**)&wH, g_w_hi);
    cudaGetSymbolAddress((void**)&wL, g_w_lo);
    cudaGetSymbolAddress((void**)&oH, g_o_hi);
    cudaGetSymbolAddress((void**)&oL, g_o_lo);
    cudaGetSymbolAddress((void**)&qh, g_qh);
    cudaGetSymbolAddress((void**)&ql, g_ql);
    cudaGetSymbolAddress((void**)&kh, g_kh);
    cudaGetSymbolAddress((void**)&kl, g_kl);
    cudaGetSymbolAddress((void**)&vh, g_vh);
    cudaGetSymbolAddress((void**)&vl, g_vl);

    const int n = S * D;
    const int sg = n / 4 / 256;
    split_kernel<<<sg, 256>>>(hs, hsH, hsL, n);
    split_kernel<<<sg, 256>>>(Wq, wH + 0 * (size_t)n, wL + 0 * (size_t)n, n);
    split_kernel<<<sg, 256>>>(Wk, wH + 1 * (size_t)n, wL + 1 * (size_t)n, n);
    split_kernel<<<sg, 256>>>(Wv, wH + 2 * (size_t)n, wL + 2 * (size_t)n, n);
    split_kernel<<<sg, 256>>>(Wo, wH + 3 * (size_t)n, wL + 3 * (size_t)n, n);

    cudaFuncSetAttribute(gemm_mma_kernel,
                         cudaFuncAttributeMaxDynamicSharedMemorySize, GSMEM);
    dim3 gg(D / 128, S / 256);
    gemm_mma_kernel<<<gg, 512, GSMEM>>>(hsH, hsL, wH + 0 * (size_t)n, wL + 0 * (size_t)n, q, 1);
    gemm_mma_kernel<<<gg, 512, GSMEM>>>(hsH, hsL, wH + 1 * (size_t)n, wL + 1 * (size_t)n, k, 1);
    gemm_mma_kernel<<<gg, 512, GSMEM>>>(hsH, hsL, wH + 2 * (size_t)n, wL + 2 * (size_t)n, v, 1);

    rope_split_kernel<<<dim3(S, H), 128>>>(q, k, v, cosT, sinT, lk, lv,
                                           qh, ql, kh, kl, vh, vl);

    int fsmem = 2 * QMAT + 2 * 4 * KVMAT;
    cudaFuncSetAttribute(flash_mma_kernel,
                         cudaFuncAttributeMaxDynamicSharedMemorySize, fsmem);
    flash_mma_kernel<<<dim3(16, 16), 256, fsmem>>>(qh, ql, kh, kl, vh, vl, oH, oL);

    gemm_mma_kernel<<<gg, 512, GSMEM>>>(oH, oL, wH + 3 * (size_t)n, wL + 3 * (size_t)n, out, 0);
}

// round 9
// speedup vs baseline: 1.4112x; 1.4112x over previous
#include <cuda_runtime.h>
#include <cuda_fp16.h>
#include <cstdint>
#include <math.h>

#define S 2048
#define D 2048
#define H 16
#define HD 128

// ---- scratch (allocation-free rule: __device__ globals) ----
__device__ float g_q[H * S * HD];
__device__ float g_k[H * S * HD];
__device__ float g_v[H * S * HD];
__device__ __half g_hs_hi[S * D], g_hs_lo[S * D];
__device__ __half g_w_hi[4][D * D];
__device__ __half g_o_hi[S * D], g_o_lo[S * D];
__device__ __half g_qh[H * S * HD], g_ql[H * S * HD];
__device__ __half g_kh[H * S * HD];
__device__ __half g_vh[H * S * HD];

// ============================================================
// helpers (arch-agnostic: mma.sync / ldmatrix / cp.async)
// ============================================================
__device__ __forceinline__ uint32_t smem_u32(const void* p) {
    uint32_t a;
    asm("{ .reg .u64 t; cvta.to.shared.u64 t, %1; cvt.u32.u64 %0, t; }"
        : "=r"(a) : "l"(p));
    return a;
}
__device__ __forceinline__ void mma16816(float* c, const uint32_t* a,
                                         const uint32_t* b) {
    asm volatile(
        "mma.sync.aligned.m16n8k16.row.col.f32.f16.f16.f32 "
        "{%0,%1,%2,%3}, {%4,%5,%6,%7}, {%8,%9}, {%0,%1,%2,%3};"
        : "+f"(c[0]), "+f"(c[1]), "+f"(c[2]), "+f"(c[3])
        : "r"(a[0]), "r"(a[1]), "r"(a[2]), "r"(a[3]), "r"(b[0]), "r"(b[1]));
}
__device__ __forceinline__ void ldsm4(uint32_t* r, uint32_t addr) {
    asm volatile("ldmatrix.sync.aligned.m8n8.x4.shared.b16 {%0,%1,%2,%3}, [%4];"
                 : "=r"(r[0]), "=r"(r[1]), "=r"(r[2]), "=r"(r[3]) : "r"(addr));
}
__device__ __forceinline__ void ldsm4t(uint32_t* r, uint32_t addr) {
    asm volatile("ldmatrix.sync.aligned.m8n8.x4.trans.shared.b16 {%0,%1,%2,%3}, [%4];"
                 : "=r"(r[0]), "=r"(r[1]), "=r"(r[2]), "=r"(r[3]) : "r"(addr));
}
#define CPASYNC16(sa, ga) \
    asm volatile("cp.async.cg.shared.global [%0], [%1], 16;" \
                 :: "r"(sa), "l"(ga) : "memory")
#define CP_COMMIT() asm volatile("cp.async.commit_group;" ::: "memory")
#define CP_WAIT(N)  asm volatile("cp.async.wait_group %0;" :: "n"(N) : "memory")

__device__ __forceinline__ uint32_t pk2h(float a, float b) {
    __half2 t = __floats2half2_rn(a, b);
    return *(uint32_t*)&t;
}

// ============================================================
// fp32 -> (hi, lo) fp16 split; and hi-only convert
// ============================================================
__global__ __launch_bounds__(256) void split_kernel(
    const float* __restrict__ x, __half* __restrict__ hi,
    __half* __restrict__ lo, int n)
{
    int i = (blockIdx.x * 256 + threadIdx.x) * 4;
    if (i >= n) return;
    float4 v = *(const float4*)(x + i);
    float f[4] = {v.x, v.y, v.z, v.w};
    __half hb[4], lb[4];
#pragma unroll
    for (int j = 0; j < 4; j++) {
        hb[j] = __float2half_rn(f[j]);
        lb[j] = __float2half_rn(f[j] - __half2float(hb[j]));
    }
    ((__half2*)(hi + i))[0] = __half2(hb[0], hb[1]);
    ((__half2*)(hi + i))[1] = __half2(hb[2], hb[3]);
    ((__half2*)(lo + i))[0] = __half2(lb[0], lb[1]);
    ((__half2*)(lo + i))[1] = __half2(lb[2], lb[3]);
}

__global__ __launch_bounds__(256) void conv_kernel(
    const float* __restrict__ x, __half* __restrict__ hi, int n)
{
    int i = (blockIdx.x * 256 + threadIdx.x) * 4;
    if (i >= n) return;
    float4 v = *(const float4*)(x + i);
    ((__half2*)(hi + i))[0] = __floats2half2_rn(v.x, v.y);
    ((__half2*)(hi + i))[1] = __floats2half2_rn(v.z, v.w);
}

// ============================================================
// mma.sync 2-term fp16 GEMM: C = (Ahi+Alo) @ Bhi^T, 2048^3.
// CTA tile 128x128, 256 thr, K-stage 64, double-buffered,
// pitch 144B.  headmode=1: per-head C layout.
// ============================================================
#define PITCH 144
#define MATSZ (128 * PITCH)      // 18432
#define STAGESZ (3 * MATSZ)      // 55296
#define GSMEM (2 * STAGESZ)      // 110592

__global__ __launch_bounds__(256, 1) void gemm_mma_kernel(
    const __half* __restrict__ Ahi, const __half* __restrict__ Alo,
    const __half* __restrict__ Bhi,
    float* __restrict__ C, int headmode)
{
    extern __shared__ char smem[];
    const uint32_t sb = smem_u32(smem);
    const int t = threadIdx.x;
    const int lane = t & 31;
    const int w = t >> 5;
    const int mw = (w >> 1) * 32;
    const int nw = (w & 1) * 64;
    const int mbase = blockIdx.y * 128;
    const int nbase = blockIdx.x * 128;

    const __half* mats[3] = {
        Ahi + (size_t)mbase * 2048, Alo + (size_t)mbase * 2048,
        Bhi + (size_t)nbase * 2048 };

    float acc[2][8][4];
#pragma unroll
    for (int i = 0; i < 2; i++)
#pragma unroll
        for (int j = 0; j < 8; j++)
#pragma unroll
            for (int k = 0; k < 4; k++) acc[i][j][k] = 0.f;

    // stage: 3 mats x 128 rows x 64 fp16 (128B data, 144B pitch)
#define LOAD_STAGE(sidx, k0) do {                                            \
        uint32_t base = sb + ((sidx) & 1) * STAGESZ;                         \
        _Pragma("unroll")                                                    \
        for (int mat = 0; mat < 3; mat++) {                                  \
            _Pragma("unroll")                                                \
            for (int r = 0; r < 4; r++) {                                    \
                int idx = t + 256 * r;                                       \
                int row = idx >> 3, c = idx & 7;                             \
                CPASYNC16(base + mat * MATSZ + row * PITCH + c * 16,         \
                          mats[mat] + (size_t)row * 2048 + (k0) + c * 8);    \
            }                                                                \
        }                                                                    \
        CP_COMMIT();                                                         \
    } while (0)

    LOAD_STAGE(0, 0);

    for (int s = 0; s < 32; s++) {
        if (s < 31) { LOAD_STAGE(s + 1, (s + 1) * 64); CP_WAIT(1); }
        else        { CP_WAIT(0); }
        __syncthreads();
        const uint32_t base = sb + (s & 1) * STAGESZ;
        const uint32_t aHiB = base;
        const uint32_t aLoB = base + MATSZ;
        const uint32_t bHiB = base + 2 * MATSZ;
#pragma unroll
        for (int ks = 0; ks < 4; ks++) {
            uint32_t a_hi[2][4], a_lo[2][4], b_hi[8][2];
#pragma unroll
            for (int mt = 0; mt < 2; mt++) {
                int row = mw + mt * 16 + (lane & 15);
                int chunk = 2 * ks + (lane >> 4);
                uint32_t off = row * PITCH + chunk * 16;
                ldsm4(a_hi[mt], aHiB + off);
                ldsm4(a_lo[mt], aLoB + off);
            }
#pragma unroll
            for (int j = 0; j < 4; j++) {
                int row = nw + j * 16 + ((lane >> 4) << 3) + (lane & 7);
                int chunk = 2 * ks + ((lane >> 3) & 1);
                uint32_t off = row * PITCH + chunk * 16;
                uint32_t rh[4];
                ldsm4(rh, bHiB + off);
                b_hi[2 * j][0] = rh[0]; b_hi[2 * j][1] = rh[1];
                b_hi[2 * j + 1][0] = rh[2]; b_hi[2 * j + 1][1] = rh[3];
            }
            // 2 terms, term-outermost over 16 independent accs
#pragma unroll
            for (int mt = 0; mt < 2; mt++)
#pragma unroll
                for (int nt = 0; nt < 8; nt++)
                    mma16816(acc[mt][nt], a_hi[mt], b_hi[nt]);
#pragma unroll
            for (int mt = 0; mt < 2; mt++)
#pragma unroll
                for (int nt = 0; nt < 8; nt++)
                    mma16816(acc[mt][nt], a_lo[mt], b_hi[nt]);
        }
        __syncthreads();
    }

#pragma unroll
    for (int mt = 0; mt < 2; mt++)
#pragma unroll
        for (int nt = 0; nt < 8; nt++) {
            const float* a = acc[mt][nt];
            int r0 = mbase + mw + mt * 16 + (lane >> 2);
            int n  = nbase + nw + nt * 8 + 2 * (lane & 3);
            if (headmode) {
                float* p0 = C + ((size_t)(n >> 7) * 2048 + r0) * 128 + (n & 127);
                float* p1 = C + ((size_t)(n >> 7) * 2048 + r0 + 8) * 128 + (n & 127);
                *(float2*)p0 = make_float2(a[0], a[1]);
                *(float2*)p1 = make_float2(a[2], a[3]);
            } else {
                *(float2*)(C + (size_t)r0 * 2048 + n)       = make_float2(a[0], a[1]);
                *(float2*)(C + (size_t)(r0 + 8) * 2048 + n) = make_float2(a[2], a[3]);
            }
        }
}

// ============================================================
// RoPE + IA3 + scale; emits: q split (hi,lo), k hi, v hi.
// ============================================================
__global__ __launch_bounds__(128) void rope_split_kernel(
    const float* __restrict__ Qm, const float* __restrict__ Km,
    const float* __restrict__ Vm,
    const float* __restrict__ cosT, const float* __restrict__ sinT,
    const float* __restrict__ lk, const float* __restrict__ lv,
    __half* __restrict__ qh, __half* __restrict__ ql,
    __half* __restrict__ kh, __half* __restrict__ vh)
{
    const int s = blockIdx.x;
    const int h = blockIdx.y;
    const int d = threadIdx.x;
    const float scale = 0.08838834764831845f;   // 1/sqrt(128)
    size_t rb = ((size_t)h * S + s) * HD;
    float c  = cosT[s * HD + d];
    float sn = sinT[s * HD + d];
    int   p  = d ^ 64;
    float sign = (d < 64) ? -1.f : 1.f;
    float q = (Qm[rb + d] * c + sign * Qm[rb + p] * sn) * lk[h * HD + d] * scale;
    float k = Km[rb + d] * c + sign * Km[rb + p] * sn;
    float v = Vm[rb + d] * lv[h * HD + d];
    __half qH = __float2half_rn(q);
    qh[rb + d] = qH;
    ql[rb + d] = __float2half_rn(q - __half2float(qH));
    kh[rb + d] = __float2half_rn(k);
    vh[rb + d] = __float2half_rn(v);
}

// ============================================================
// Causal flash attention, mma.sync 2-term fp16.
// BQ=128, BK=64, 8 warps, double-buffered {Kh,Vh}.
// Epilogue emits split fp16 O.
// ============================================================
#define FPB 272
#define QMAT (128 * FPB)
#define KVMAT (64 * FPB)

__global__ __launch_bounds__(256, 1) void flash_mma_kernel(
    const __half* __restrict__ Qh_, const __half* __restrict__ Ql_,
    const __half* __restrict__ Kh_, const __half* __restrict__ Vh_,
    __half* __restrict__ OH, __half* __restrict__ OL)
{
    extern __shared__ char smem[];
    const uint32_t sb = smem_u32(smem);
    const int t = threadIdx.x, lane = t & 31, w = t >> 5;
    const int qt = 15 - (int)blockIdx.x;
    const int h = blockIdx.y;
    const int mw = w * 16;
    const size_t hoff = (size_t)h * S * HD;
    const __half* Qhp = Qh_ + hoff + (size_t)qt * 128 * HD;
    const __half* Qlp = Ql_ + hoff + (size_t)qt * 128 * HD;
    const __half* Khp = Kh_ + hoff;
    const __half* Vhp = Vh_ + hoff;

    const uint32_t qB  = sb;                 // Qhi; Qlo at +QMAT
    const uint32_t kvB = sb + 2 * QMAT;      // stages: {Kh, Vh} x2

#pragma unroll
    for (int r = 0; r < 8; r++) {
        int idx = t + 256 * r;
        int row = idx >> 4, c = idx & 15;
        CPASYNC16(qB + row * FPB + c * 16,        Qhp + row * 128 + c * 8);
        CPASYNC16(qB + QMAT + row * FPB + c * 16, Qlp + row * 128 + c * 8);
    }
    CP_COMMIT();

#define LOADKV(kt_, p_) do {                                                  \
        uint32_t b_ = kvB + (p_) * (2 * KVMAT);                               \
        const __half* g0 = Khp + (size_t)(kt_) * 64 * 128;                    \
        const __half* g1 = Vhp + (size_t)(kt_) * 64 * 128;                    \
        _Pragma("unroll")                                                     \
        for (int r_ = 0; r_ < 4; r_++) {                                      \
            int idx_ = t + 256 * r_;                                          \
            int row_ = idx_ >> 4, c_ = idx_ & 15;                             \
            uint32_t so_ = row_ * FPB + c_ * 16;                              \
            uint32_t go_ = row_ * 128 + c_ * 8;                               \
            CPASYNC16(b_ + so_,         g0 + go_);                            \
            CPASYNC16(b_ + KVMAT + so_, g1 + go_);                            \
        }                                                                     \
        CP_COMMIT();                                                          \
    } while (0)

    float acc[16][4];
#pragma unroll
    for (int i = 0; i < 16; i++)
#pragma unroll
        for (int j = 0; j < 4; j++) acc[i][j] = 0.f;
    float m0 = -1e30f, m1 = -1e30f, l0 = 0.f, l1 = 0.f;

    const int ktmax = 2 * qt + 1;
    LOADKV(0, 0);

    for (int kt = 0; kt <= ktmax; kt++) {
        if (kt < ktmax) { LOADKV(kt + 1, (kt + 1) & 1); CP_WAIT(1); }
        else            { CP_WAIT(0); }
        __syncthreads();
        const uint32_t base = kvB + (kt & 1) * (2 * KVMAT);

        // ---- S = (Qh+Ql) @ Kh^T ----
        float s[8][4];
#pragma unroll
        for (int i = 0; i < 8; i++)
#pragma unroll
            for (int j = 0; j < 4; j++) s[i][j] = 0.f;
#pragma unroll
        for (int kc = 0; kc < 8; kc++) {
            uint32_t aH[4], aL[4];
            uint32_t aaddr = qB + (mw + (lane & 15)) * FPB + (2 * kc + (lane >> 4)) * 16;
            ldsm4(aH, aaddr);
            ldsm4(aL, aaddr + QMAT);
            uint32_t bH[8][2];
#pragma unroll
            for (int j = 0; j < 4; j++) {
                int row = j * 16 + ((lane >> 4) << 3) + (lane & 7);
                uint32_t baddr = base + row * FPB + (2 * kc + ((lane >> 3) & 1)) * 16;
                uint32_t rh[4];
                ldsm4(rh, baddr);
                bH[2 * j][0] = rh[0]; bH[2 * j][1] = rh[1];
                bH[2 * j + 1][0] = rh[2]; bH[2 * j + 1][1] = rh[3];
            }
#pragma unroll
            for (int nb = 0; nb < 8; nb++)
                mma16816(s[nb], aH, bH[nb]);
#pragma unroll
            for (int nb = 0; nb < 8; nb++)
                mma16816(s[nb], aL, bH[nb]);
        }

        const int qrow = qt * 128 + mw + (lane >> 2);
        if (kt * 64 + 63 > qt * 128 + mw) {
#pragma unroll
            for (int nb = 0; nb < 8; nb++) {
                int col = kt * 64 + 8 * nb + 2 * (lane & 3);
                if (col     > qrow)     s[nb][0] = -1e30f;
                if (col + 1 > qrow)     s[nb][1] = -1e30f;
                if (col     > qrow + 8) s[nb][2] = -1e30f;
                if (col + 1 > qrow + 8) s[nb][3] = -1e30f;
            }
        }

        float mx0 = -1e30f, mx1 = -1e30f;
#pragma unroll
        for (int nb = 0; nb < 8; nb++) {
            mx0 = fmaxf(mx0, fmaxf(s[nb][0], s[nb][1]));
            mx1 = fmaxf(mx1, fmaxf(s[nb][2], s[nb][3]));
        }
        mx0 = fmaxf(mx0, __shfl_xor_sync(0xffffffffu, mx0, 1));
        mx0 = fmaxf(mx0, __shfl_xor_sync(0xffffffffu, mx0, 2));
        mx1 = fmaxf(mx1, __shfl_xor_sync(0xffffffffu, mx1, 1));
        mx1 = fmaxf(mx1, __shfl_xor_sync(0xffffffffu, mx1, 2));
        float mn0 = fmaxf(m0, mx0), mn1 = fmaxf(m1, mx1);
        float al0 = __expf(m0 - mn0), al1 = __expf(m1 - mn1);
        m0 = mn0; m1 = mn1;

        // ---- P split to fp16 hi/lo in registers ----
        float sum0 = 0.f, sum1 = 0.f;
        uint32_t ph0[8], ph1[8], pl0[8], pl1[8];
#pragma unroll
        for (int nb = 0; nb < 8; nb++) {
            float p0 = __expf(s[nb][0] - mn0), p1 = __expf(s[nb][1] - mn0);
            float p2 = __expf(s[nb][2] - mn1), p3 = __expf(s[nb][3] - mn1);
            sum0 += p0 + p1; sum1 += p2 + p3;
            __half2 h01 = __floats2half2_rn(p0, p1);
            __half2 h23 = __floats2half2_rn(p2, p3);
            ph0[nb] = *(uint32_t*)&h01;
            ph1[nb] = *(uint32_t*)&h23;
            pl0[nb] = pk2h(p0 - __half2float(h01.x), p1 - __half2float(h01.y));
            pl1[nb] = pk2h(p2 - __half2float(h23.x), p3 - __half2float(h23.y));
        }
        sum0 += __shfl_xor_sync(0xffffffffu, sum0, 1);
        sum0 += __shfl_xor_sync(0xffffffffu, sum0, 2);
        sum1 += __shfl_xor_sync(0xffffffffu, sum1, 1);
        sum1 += __shfl_xor_sync(0xffffffffu, sum1, 2);
        l0 = l0 * al0 + sum0;
        l1 = l1 * al1 + sum1;
#pragma unroll
        for (int nb = 0; nb < 16; nb++) {
            acc[nb][0] *= al0; acc[nb][1] *= al0;
            acc[nb][2] *= al1; acc[nb][3] *= al1;
        }

        // ---- O += (Ph+Pl) @ Vh ----
#pragma unroll
        for (int kc = 0; kc < 4; kc++) {
            uint32_t paH[4] = {ph0[2 * kc], ph1[2 * kc], ph0[2 * kc + 1], ph1[2 * kc + 1]};
            uint32_t paL[4] = {pl0[2 * kc], pl1[2 * kc], pl0[2 * kc + 1], pl1[2 * kc + 1]};
#pragma unroll
            for (int nb2 = 0; nb2 < 8; nb2++) {
                uint32_t vaddr = base + KVMAT +
                                 (kc * 16 + (lane & 15)) * FPB + (2 * nb2 + (lane >> 4)) * 16;
                uint32_t vh[4];
                ldsm4t(vh, vaddr);
                uint32_t bh0[2] = {vh[0], vh[1]}, bh1[2] = {vh[2], vh[3]};
                mma16816(acc[2 * nb2], paH, bh0);
                mma16816(acc[2 * nb2 + 1], paH, bh1);
                mma16816(acc[2 * nb2], paL, bh0);
                mma16816(acc[2 * nb2 + 1], paL, bh1);
            }
        }
        __syncthreads();
    }

    // ---- epilogue: normalize, split to fp16 hi/lo, write ----
    float inv0 = 1.f / l0, inv1 = 1.f / l1;
    int r = qt * 128 + mw + (lane >> 2);
#pragma unroll
    for (int nb = 0; nb < 16; nb++) {
        int col = h * 128 + 8 * nb + 2 * (lane & 3);
        float v0 = acc[nb][0] * inv0, v1 = acc[nb][1] * inv0;
        float v2 = acc[nb][2] * inv1, v3 = acc[nb][3] * inv1;
        __half2 h01 = __floats2half2_rn(v0, v1);
        __half2 h23 = __floats2half2_rn(v2, v3);
        __half2 l01 = __floats2half2_rn(
            v0 - __half2float(h01.x), v1 - __half2float(h01.y));
        __half2 l23 = __floats2half2_rn(
            v2 - __half2float(h23.x), v3 - __half2float(h23.y));
        *(__half2*)&OH[(size_t)r * D + col]       = h01;
        *(__half2*)&OL[(size_t)r * D + col]       = l01;
        *(__half2*)&OH[(size_t)(r + 8) * D + col] = h23;
        *(__half2*)&OL[(size_t)(r + 8) * D + col] = l23;
    }
}

// ============================================================
extern "C" void kernel_launch(void* const* d_in, const int* in_sizes, int n_in,
                              void* d_out, int out_size)
{
    const float* hs   = (const float*)d_in[0];
    const float* cosT = (const float*)d_in[2];
    const float* sinT = (const float*)d_in[3];
    const float* Wq   = (const float*)d_in[4];
    const float* Wk   = (const float*)d_in[5];
    const float* Wv   = (const float*)d_in[6];
    const float* Wo   = (const float*)d_in[7];
    const float* lk   = (const float*)d_in[8];
    const float* lv   = (const float*)d_in[9];
    float* out = (float*)d_out;
    (void)in_sizes; (void)n_in; (void)out_size;

    float *q, *k, *v;
    cudaGetSymbolAddress((void**)&q, g_q);
    cudaGetSymbolAddress((void**)&k, g_k);
    cudaGetSymbolAddress((void**)&v, g_v);
    __half *hsH, *hsL, *wH, *oH, *oL, *qh, *ql, *kh, *vh;
    cudaGetSymbolAddress((void**)&hsH, g_hs_hi);
    cudaGetSymbolAddress((void**)&hsL, g_hs_lo);
    cudaGetSymbolAddress((void**)&wH, g_w_hi);
    cudaGetSymbolAddress((void**)&oH, g_o_hi);
    cudaGetSymbolAddress((void**)&oL, g_o_lo);
    cudaGetSymbolAddress((void**)&qh, g_qh);
    cudaGetSymbolAddress((void**)&ql, g_ql);
    cudaGetSymbolAddress((void**)&kh, g_kh);
    cudaGetSymbolAddress((void**)&vh, g_vh);

    const int n = S * D;
    const int sg = n / 4 / 256;
    split_kernel<<<sg, 256>>>(hs, hsH, hsL, n);
    conv_kernel<<<sg, 256>>>(Wq, wH + 0 * (size_t)n, n);
    conv_kernel<<<sg, 256>>>(Wk, wH + 1 * (size_t)n, n);
    conv_kernel<<<sg, 256>>>(Wv, wH + 2 * (size_t)n, n);
    conv_kernel<<<sg, 256>>>(Wo, wH + 3 * (size_t)n, n);

    cudaFuncSetAttribute(gemm_mma_kernel,
                         cudaFuncAttributeMaxDynamicSharedMemorySize, GSMEM);
    dim3 gg(D / 128, S / 128);
    gemm_mma_kernel<<<gg, 256, GSMEM>>>(hsH, hsL, wH + 0 * (size_t)n, q, 1);
    gemm_mma_kernel<<<gg, 256, GSMEM>>>(hsH, hsL, wH + 1 * (size_t)n, k, 1);
    gemm_mma_kernel<<<gg, 256, GSMEM>>>(hsH, hsL, wH + 2 * (size_t)n, v, 1);

    rope_split_kernel<<<dim3(S, H), 128>>>(q, k, v, cosT, sinT, lk, lv,
                                           qh, ql, kh, vh);

    int fsmem = 2 * QMAT + 2 * 2 * KVMAT;   // 139264
    cudaFuncSetAttribute(flash_mma_kernel,
                         cudaFuncAttributeMaxDynamicSharedMemorySize, fsmem);
    flash_mma_kernel<<<dim3(16, 16), 256, fsmem>>>(qh, ql, kh, vh, oH, oL);

    gemm_mma_kernel<<<gg, 256, GSMEM>>>(oH, oL, wH + 3 * (size_t)n, out, 0);
}

// round 10
// speedup vs baseline: 2.2535x; 1.5968x over previous
#include <cuda_runtime.h>
#include <cuda_fp16.h>
#include <cstdint>
#include <math.h>

#define S 2048
#define D 2048
#define H 16
#define HD 128

// ---- scratch (allocation-free rule: __device__ globals) ----
__device__ float g_q[H * S * HD];
__device__ float g_k[H * S * HD];
__device__ float g_v[H * S * HD];
__device__ __half g_hs_hi[S * D];
__device__ __half g_w_hi[4][D * D];
__device__ __half g_o_hi[S * D];
__device__ __half g_qh[H * S * HD];
__device__ __half g_kh[H * S * HD];
__device__ __half g_vh[H * S * HD];

// ============================================================
// helpers (arch-agnostic: mma.sync / ldmatrix / cp.async)
// ============================================================
__device__ __forceinline__ uint32_t smem_u32(const void* p) {
    uint32_t a;
    asm("{ .reg .u64 t; cvta.to.shared.u64 t, %1; cvt.u32.u64 %0, t; }"
        : "=r"(a) : "l"(p));
    return a;
}
__device__ __forceinline__ void mma16816(float* c, const uint32_t* a,
                                         const uint32_t* b) {
    asm volatile(
        "mma.sync.aligned.m16n8k16.row.col.f32.f16.f16.f32 "
        "{%0,%1,%2,%3}, {%4,%5,%6,%7}, {%8,%9}, {%0,%1,%2,%3};"
        : "+f"(c[0]), "+f"(c[1]), "+f"(c[2]), "+f"(c[3])
        : "r"(a[0]), "r"(a[1]), "r"(a[2]), "r"(a[3]), "r"(b[0]), "r"(b[1]));
}
__device__ __forceinline__ void ldsm4(uint32_t* r, uint32_t addr) {
    asm volatile("ldmatrix.sync.aligned.m8n8.x4.shared.b16 {%0,%1,%2,%3}, [%4];"
                 : "=r"(r[0]), "=r"(r[1]), "=r"(r[2]), "=r"(r[3]) : "r"(addr));
}
__device__ __forceinline__ void ldsm4t(uint32_t* r, uint32_t addr) {
    asm volatile("ldmatrix.sync.aligned.m8n8.x4.trans.shared.b16 {%0,%1,%2,%3}, [%4];"
                 : "=r"(r[0]), "=r"(r[1]), "=r"(r[2]), "=r"(r[3]) : "r"(addr));
}
#define CPASYNC16(sa, ga) \
    asm volatile("cp.async.cg.shared.global [%0], [%1], 16;" \
                 :: "r"(sa), "l"(ga) : "memory")
#define CP_COMMIT() asm volatile("cp.async.commit_group;" ::: "memory")
#define CP_WAIT(N)  asm volatile("cp.async.wait_group %0;" :: "n"(N) : "memory")

// ============================================================
// fp32 -> fp16 convert
// ============================================================
__global__ __launch_bounds__(256) void conv_kernel(
    const float* __restrict__ x, __half* __restrict__ hi, int n)
{
    int i = (blockIdx.x * 256 + threadIdx.x) * 4;
    if (i >= n) return;
    float4 v = *(const float4*)(x + i);
    ((__half2*)(hi + i))[0] = __floats2half2_rn(v.x, v.y);
    ((__half2*)(hi + i))[1] = __floats2half2_rn(v.z, v.w);
}

// ============================================================
// mma.sync 1-term fp16 GEMM: C = Ah @ Bh^T, 2048^3.
// CTA tile 128x128, 256 thr, K-stage 64, double-buffered,
// pitch 144B.  headmode=1: per-head C layout.
// ============================================================
#define PITCH 144
#define MATSZ (128 * PITCH)      // 18432
#define STAGESZ (2 * MATSZ)      // 36864
#define GSMEM (2 * STAGESZ)      // 73728

__global__ __launch_bounds__(256) void gemm_mma_kernel(
    const __half* __restrict__ Ahi, const __half* __restrict__ Bhi,
    float* __restrict__ C, int headmode)
{
    extern __shared__ char smem[];
    const uint32_t sb = smem_u32(smem);
    const int t = threadIdx.x;
    const int lane = t & 31;
    const int w = t >> 5;
    const int mw = (w >> 1) * 32;
    const int nw = (w & 1) * 64;
    const int mbase = blockIdx.y * 128;
    const int nbase = blockIdx.x * 128;

    const __half* mats[2] = {
        Ahi + (size_t)mbase * 2048, Bhi + (size_t)nbase * 2048 };

    float acc[2][8][4];
#pragma unroll
    for (int i = 0; i < 2; i++)
#pragma unroll
        for (int j = 0; j < 8; j++)
#pragma unroll
            for (int k = 0; k < 4; k++) acc[i][j][k] = 0.f;

    // stage: 2 mats x 128 rows x 64 fp16 (128B data, 144B pitch)
#define LOAD_STAGE(sidx, k0) do {                                            \
        uint32_t base = sb + ((sidx) & 1) * STAGESZ;                         \
        _Pragma("unroll")                                                    \
        for (int mat = 0; mat < 2; mat++) {                                  \
            _Pragma("unroll")                                                \
            for (int r = 0; r < 4; r++) {                                    \
                int idx = t + 256 * r;                                       \
                int row = idx >> 3, c = idx & 7;                             \
                CPASYNC16(base + mat * MATSZ + row * PITCH + c * 16,         \
                          mats[mat] + (size_t)row * 2048 + (k0) + c * 8);    \
            }                                                                \
        }                                                                    \
        CP_COMMIT();                                                         \
    } while (0)

    LOAD_STAGE(0, 0);

    for (int s = 0; s < 32; s++) {
        if (s < 31) { LOAD_STAGE(s + 1, (s + 1) * 64); CP_WAIT(1); }
        else        { CP_WAIT(0); }
        __syncthreads();
        const uint32_t base = sb + (s & 1) * STAGESZ;
        const uint32_t aHiB = base;
        const uint32_t bHiB = base + MATSZ;
#pragma unroll
        for (int ks = 0; ks < 4; ks++) {
            uint32_t a_hi[2][4], b_hi[8][2];
#pragma unroll
            for (int mt = 0; mt < 2; mt++) {
                int row = mw + mt * 16 + (lane & 15);
                int chunk = 2 * ks + (lane >> 4);
                ldsm4(a_hi[mt], aHiB + row * PITCH + chunk * 16);
            }
#pragma unroll
            for (int j = 0; j < 4; j++) {
                int row = nw + j * 16 + ((lane >> 4) << 3) + (lane & 7);
                int chunk = 2 * ks + ((lane >> 3) & 1);
                uint32_t rh[4];
                ldsm4(rh, bHiB + row * PITCH + chunk * 16);
                b_hi[2 * j][0] = rh[0]; b_hi[2 * j][1] = rh[1];
                b_hi[2 * j + 1][0] = rh[2]; b_hi[2 * j + 1][1] = rh[3];
            }
#pragma unroll
            for (int mt = 0; mt < 2; mt++)
#pragma unroll
                for (int nt = 0; nt < 8; nt++)
                    mma16816(acc[mt][nt], a_hi[mt], b_hi[nt]);
        }
        __syncthreads();
    }

#pragma unroll
    for (int mt = 0; mt < 2; mt++)
#pragma unroll
        for (int nt = 0; nt < 8; nt++) {
            const float* a = acc[mt][nt];
            int r0 = mbase + mw + mt * 16 + (lane >> 2);
            int n  = nbase + nw + nt * 8 + 2 * (lane & 3);
            if (headmode) {
                float* p0 = C + ((size_t)(n >> 7) * 2048 + r0) * 128 + (n & 127);
                float* p1 = C + ((size_t)(n >> 7) * 2048 + r0 + 8) * 128 + (n & 127);
                *(float2*)p0 = make_float2(a[0], a[1]);
                *(float2*)p1 = make_float2(a[2], a[3]);
            } else {
                *(float2*)(C + (size_t)r0 * 2048 + n)       = make_float2(a[0], a[1]);
                *(float2*)(C + (size_t)(r0 + 8) * 2048 + n) = make_float2(a[2], a[3]);
            }
        }
}

// ============================================================
// RoPE + IA3 + scale; emits fp16 q, k, v.
// ============================================================
__global__ __launch_bounds__(128) void rope_conv_kernel(
    const float* __restrict__ Qm, const float* __restrict__ Km,
    const float* __restrict__ Vm,
    const float* __restrict__ cosT, const float* __restrict__ sinT,
    const float* __restrict__ lk, const float* __restrict__ lv,
    __half* __restrict__ qh, __half* __restrict__ kh, __half* __restrict__ vh)
{
    const int s = blockIdx.x;
    const int h = blockIdx.y;
    const int d = threadIdx.x;
    const float scale = 0.08838834764831845f;   // 1/sqrt(128)
    size_t rb = ((size_t)h * S + s) * HD;
    float c  = cosT[s * HD + d];
    float sn = sinT[s * HD + d];
    int   p  = d ^ 64;
    float sign = (d < 64) ? -1.f : 1.f;
    float q = (Qm[rb + d] * c + sign * Qm[rb + p] * sn) * lk[h * HD + d] * scale;
    float k = Km[rb + d] * c + sign * Km[rb + p] * sn;
    float v = Vm[rb + d] * lv[h * HD + d];
    qh[rb + d] = __float2half_rn(q);
    kh[rb + d] = __float2half_rn(k);
    vh[rb + d] = __float2half_rn(v);
}

// ============================================================
// Causal flash attention, mma.sync 1-term fp16.
// BQ=128, BK=64, 8 warps, double-buffered {Kh,Vh}.
// ============================================================
#define FPB 272
#define QMAT (128 * FPB)
#define KVMAT (64 * FPB)

__global__ __launch_bounds__(256) void flash_mma_kernel(
    const __half* __restrict__ Qh_, const __half* __restrict__ Kh_,
    const __half* __restrict__ Vh_, __half* __restrict__ OH)
{
    extern __shared__ char smem[];
    const uint32_t sb = smem_u32(smem);
    const int t = threadIdx.x, lane = t & 31, w = t >> 5;
    const int qt = 15 - (int)blockIdx.x;
    const int h = blockIdx.y;
    const int mw = w * 16;
    const size_t hoff = (size_t)h * S * HD;
    const __half* Qhp = Qh_ + hoff + (size_t)qt * 128 * HD;
    const __half* Khp = Kh_ + hoff;
    const __half* Vhp = Vh_ + hoff;

    const uint32_t qB  = sb;
    const uint32_t kvB = sb + QMAT;      // stages: {Kh, Vh} x2

#pragma unroll
    for (int r = 0; r < 8; r++) {
        int idx = t + 256 * r;
        int row = idx >> 4, c = idx & 15;
        CPASYNC16(qB + row * FPB + c * 16, Qhp + row * 128 + c * 8);
    }
    CP_COMMIT();

#define LOADKV(kt_, p_) do {                                                  \
        uint32_t b_ = kvB + (p_) * (2 * KVMAT);                               \
        const __half* g0 = Khp + (size_t)(kt_) * 64 * 128;                    \
        const __half* g1 = Vhp + (size_t)(kt_) * 64 * 128;                    \
        _Pragma("unroll")                                                     \
        for (int r_ = 0; r_ < 4; r_++) {                                      \
            int idx_ = t + 256 * r_;                                          \
            int row_ = idx_ >> 4, c_ = idx_ & 15;                             \
            uint32_t so_ = row_ * FPB + c_ * 16;                              \
            uint32_t go_ = row_ * 128 + c_ * 8;                               \
            CPASYNC16(b_ + so_,         g0 + go_);                            \
            CPASYNC16(b_ + KVMAT + so_, g1 + go_);                            \
        }                                                                     \
        CP_COMMIT();                                                          \
    } while (0)

    float acc[16][4];
#pragma unroll
    for (int i = 0; i < 16; i++)
#pragma unroll
        for (int j = 0; j < 4; j++) acc[i][j] = 0.f;
    float m0 = -1e30f, m1 = -1e30f, l0 = 0.f, l1 = 0.f;

    const int ktmax = 2 * qt + 1;
    LOADKV(0, 0);

    for (int kt = 0; kt <= ktmax; kt++) {
        if (kt < ktmax) { LOADKV(kt + 1, (kt + 1) & 1); CP_WAIT(1); }
        else            { CP_WAIT(0); }
        __syncthreads();
        const uint32_t base = kvB + (kt & 1) * (2 * KVMAT);

        // ---- S = Qh @ Kh^T ----
        float s[8][4];
#pragma unroll
        for (int i = 0; i < 8; i++)
#pragma unroll
            for (int j = 0; j < 4; j++) s[i][j] = 0.f;
#pragma unroll
        for (int kc = 0; kc < 8; kc++) {
            uint32_t aH[4];
            ldsm4(aH, qB + (mw + (lane & 15)) * FPB + (2 * kc + (lane >> 4)) * 16);
            uint32_t bH[8][2];
#pragma unroll
            for (int j = 0; j < 4; j++) {
                int row = j * 16 + ((lane >> 4) << 3) + (lane & 7);
                uint32_t rh[4];
                ldsm4(rh, base + row * FPB + (2 * kc + ((lane >> 3) & 1)) * 16);
                bH[2 * j][0] = rh[0]; bH[2 * j][1] = rh[1];
                bH[2 * j + 1][0] = rh[2]; bH[2 * j + 1][1] = rh[3];
            }
#pragma unroll
            for (int nb = 0; nb < 8; nb++)
                mma16816(s[nb], aH, bH[nb]);
        }

        const int qrow = qt * 128 + mw + (lane >> 2);
        if (kt * 64 + 63 > qt * 128 + mw) {
#pragma unroll
            for (int nb = 0; nb < 8; nb++) {
                int col = kt * 64 + 8 * nb + 2 * (lane & 3);
                if (col     > qrow)     s[nb][0] = -1e30f;
                if (col + 1 > qrow)     s[nb][1] = -1e30f;
                if (col     > qrow + 8) s[nb][2] = -1e30f;
                if (col + 1 > qrow + 8) s[nb][3] = -1e30f;
            }
        }

        float mx0 = -1e30f, mx1 = -1e30f;
#pragma unroll
        for (int nb = 0; nb < 8; nb++) {
            mx0 = fmaxf(mx0, fmaxf(s[nb][0], s[nb][1]));
            mx1 = fmaxf(mx1, fmaxf(s[nb][2], s[nb][3]));
        }
        mx0 = fmaxf(mx0, __shfl_xor_sync(0xffffffffu, mx0, 1));
        mx0 = fmaxf(mx0, __shfl_xor_sync(0xffffffffu, mx0, 2));
        mx1 = fmaxf(mx1, __shfl_xor_sync(0xffffffffu, mx1, 1));
        mx1 = fmaxf(mx1, __shfl_xor_sync(0xffffffffu, mx1, 2));
        float mn0 = fmaxf(m0, mx0), mn1 = fmaxf(m1, mx1);
        float al0 = __expf(m0 - mn0), al1 = __expf(m1 - mn1);
        m0 = mn0; m1 = mn1;

        // ---- P rounded to fp16 in registers ----
        float sum0 = 0.f, sum1 = 0.f;
        uint32_t ph0[8], ph1[8];
#pragma unroll
        for (int nb = 0; nb < 8; nb++) {
            float p0 = __expf(s[nb][0] - mn0), p1 = __expf(s[nb][1] - mn0);
            float p2 = __expf(s[nb][2] - mn1), p3 = __expf(s[nb][3] - mn1);
            sum0 += p0 + p1; sum1 += p2 + p3;
            __half2 h01 = __floats2half2_rn(p0, p1);
            __half2 h23 = __floats2half2_rn(p2, p3);
            ph0[nb] = *(uint32_t*)&h01;
            ph1[nb] = *(uint32_t*)&h23;
        }
        sum0 += __shfl_xor_sync(0xffffffffu, sum0, 1);
        sum0 += __shfl_xor_sync(0xffffffffu, sum0, 2);
        sum1 += __shfl_xor_sync(0xffffffffu, sum1, 1);
        sum1 += __shfl_xor_sync(0xffffffffu, sum1, 2);
        l0 = l0 * al0 + sum0;
        l1 = l1 * al1 + sum1;
#pragma unroll
        for (int nb = 0; nb < 16; nb++) {
            acc[nb][0] *= al0; acc[nb][1] *= al0;
            acc[nb][2] *= al1; acc[nb][3] *= al1;
        }

        // ---- O += Ph @ Vh ----
#pragma unroll
        for (int kc = 0; kc < 4; kc++) {
            uint32_t paH[4] = {ph0[2 * kc], ph1[2 * kc], ph0[2 * kc + 1], ph1[2 * kc + 1]};
#pragma unroll
            for (int nb2 = 0; nb2 < 8; nb2++) {
                uint32_t vaddr = base + KVMAT +
                                 (kc * 16 + (lane & 15)) * FPB + (2 * nb2 + (lane >> 4)) * 16;
                uint32_t vh[4];
                ldsm4t(vh, vaddr);
                uint32_t bh0[2] = {vh[0], vh[1]}, bh1[2] = {vh[2], vh[3]};
                mma16816(acc[2 * nb2], paH, bh0);
                mma16816(acc[2 * nb2 + 1], paH, bh1);
            }
        }
        __syncthreads();
    }

    // ---- epilogue: normalize, round to fp16, write ----
    float inv0 = 1.f / l0, inv1 = 1.f / l1;
    int r = qt * 128 + mw + (lane >> 2);
#pragma unroll
    for (int nb = 0; nb < 16; nb++) {
        int col = h * 128 + 8 * nb + 2 * (lane & 3);
        *(__half2*)&OH[(size_t)r * D + col] =
            __floats2half2_rn(acc[nb][0] * inv0, acc[nb][1] * inv0);
        *(__half2*)&OH[(size_t)(r + 8) * D + col] =
            __floats2half2_rn(acc[nb][2] * inv1, acc[nb][3] * inv1);
    }
}

// ============================================================
extern "C" void kernel_launch(void* const* d_in, const int* in_sizes, int n_in,
                              void* d_out, int out_size)
{
    const float* hs   = (const float*)d_in[0];
    const float* cosT = (const float*)d_in[2];
    const float* sinT = (const float*)d_in[3];
    const float* Wq   = (const float*)d_in[4];
    const float* Wk   = (const float*)d_in[5];
    const float* Wv   = (const float*)d_in[6];
    const float* Wo   = (const float*)d_in[7];
    const float* lk   = (const float*)d_in[8];
    const float* lv   = (const float*)d_in[9];
    float* out = (float*)d_out;
    (void)in_sizes; (void)n_in; (void)out_size;

    float *q, *k, *v;
    cudaGetSymbolAddress((void**)&q, g_q);
    cudaGetSymbolAddress((void**)&k, g_k);
    cudaGetSymbolAddress((void**)&v, g_v);
    __half *hsH, *wH, *oH, *qh, *kh, *vh;
    cudaGetSymbolAddress((void**)&hsH, g_hs_hi);
    cudaGetSymbolAddress((void**)&wH, g_w_hi);
    cudaGetSymbolAddress((void**)&oH, g_o_hi);
    cudaGetSymbolAddress((void**)&qh, g_qh);
    cudaGetSymbolAddress((void**)&kh, g_kh);
    cudaGetSymbolAddress((void**)&vh, g_vh);

    const int n = S * D;
    const int sg = n / 4 / 256;
    conv_kernel<<<sg, 256>>>(hs, hsH, n);
    conv_kernel<<<sg, 256>>>(Wq, wH + 0 * (size_t)n, n);
    conv_kernel<<<sg, 256>>>(Wk, wH + 1 * (size_t)n, n);
    conv_kernel<<<sg, 256>>>(Wv, wH + 2 * (size_t)n, n);
    conv_kernel<<<sg, 256>>>(Wo, wH + 3 * (size_t)n, n);

    cudaFuncSetAttribute(gemm_mma_kernel,
                         cudaFuncAttributeMaxDynamicSharedMemorySize, GSMEM);
    dim3 gg(D / 128, S / 128);
    gemm_mma_kernel<<<gg, 256, GSMEM>>>(hsH, wH + 0 * (size_t)n, q, 1);
    gemm_mma_kernel<<<gg, 256, GSMEM>>>(hsH, wH + 1 * (size_t)n, k, 1);
    gemm_mma_kernel<<<gg, 256, GSMEM>>>(hsH, wH + 2 * (size_t)n, v, 1);

    rope_conv_kernel<<<dim3(S, H), 128>>>(q, k, v, cosT, sinT, lk, lv,
                                          qh, kh, vh);

    int fsmem = QMAT + 2 * 2 * KVMAT;   // 104448
    cudaFuncSetAttribute(flash_mma_kernel,
                         cudaFuncAttributeMaxDynamicSharedMemorySize, fsmem);
    flash_mma_kernel<<<dim3(16, 16), 256, fsmem>>>(qh, kh, vh, oH);

    gemm_mma_kernel<<<gg, 256, GSMEM>>>(oH, wH + 3 * (size_t)n, out, 0);
}

// round 11
// speedup vs baseline: 2.2989x; 1.0201x over previous
#include <cuda_runtime.h>
#include <cuda_fp16.h>
#include <cstdint>
#include <math.h>

#define S 2048
#define D 2048
#define H 16
#define HD 128

// ---- scratch (allocation-free rule: __device__ globals) ----
__device__ float g_q[H * S * HD];
__device__ float g_k[H * S * HD];
__device__ __half g_hs_hi[S * D];
__device__ __half g_w_hi[4][D * D];
__device__ __half g_o_hi[S * D];
__device__ __half g_qh[H * S * HD];
__device__ __half g_kh[H * S * HD];
__device__ __half g_vh[H * S * HD];

// ============================================================
// helpers (arch-agnostic: mma.sync / ldmatrix / cp.async)
// ============================================================
__device__ __forceinline__ uint32_t smem_u32(const void* p) {
    uint32_t a;
    asm("{ .reg .u64 t; cvta.to.shared.u64 t, %1; cvt.u32.u64 %0, t; }"
        : "=r"(a) : "l"(p));
    return a;
}
__device__ __forceinline__ void mma16816(float* c, const uint32_t* a,
                                         const uint32_t* b) {
    asm volatile(
        "mma.sync.aligned.m16n8k16.row.col.f32.f16.f16.f32 "
        "{%0,%1,%2,%3}, {%4,%5,%6,%7}, {%8,%9}, {%0,%1,%2,%3};"
        : "+f"(c[0]), "+f"(c[1]), "+f"(c[2]), "+f"(c[3])
        : "r"(a[0]), "r"(a[1]), "r"(a[2]), "r"(a[3]), "r"(b[0]), "r"(b[1]));
}
__device__ __forceinline__ void ldsm4(uint32_t* r, uint32_t addr) {
    asm volatile("ldmatrix.sync.aligned.m8n8.x4.shared.b16 {%0,%1,%2,%3}, [%4];"
                 : "=r"(r[0]), "=r"(r[1]), "=r"(r[2]), "=r"(r[3]) : "r"(addr));
}
__device__ __forceinline__ void ldsm4t(uint32_t* r, uint32_t addr) {
    asm volatile("ldmatrix.sync.aligned.m8n8.x4.trans.shared.b16 {%0,%1,%2,%3}, [%4];"
                 : "=r"(r[0]), "=r"(r[1]), "=r"(r[2]), "=r"(r[3]) : "r"(addr));
}
#define CPASYNC16(sa, ga) \
    asm volatile("cp.async.cg.shared.global [%0], [%1], 16;" \
                 :: "r"(sa), "l"(ga) : "memory")
#define CP_COMMIT() asm volatile("cp.async.commit_group;" ::: "memory")
#define CP_WAIT(N)  asm volatile("cp.async.wait_group %0;" :: "n"(N) : "memory")

// ============================================================
// fused fp32 -> fp16 convert for 5 tensors (hs + 4 weights)
// ============================================================
__global__ __launch_bounds__(256) void conv5_kernel(
    const float* __restrict__ s0, const float* __restrict__ s1,
    const float* __restrict__ s2, const float* __restrict__ s3,
    const float* __restrict__ s4,
    __half* __restrict__ hsH, __half* __restrict__ wH, int n)
{
    int gi = blockIdx.x * 256 + threadIdx.x;
    int per = n / 4;                 // threads per tensor
    int sel = gi / per;
    int i = (gi - sel * per) * 4;
    const float* src = (sel == 0) ? s0 : (sel == 1) ? s1 :
                       (sel == 2) ? s2 : (sel == 3) ? s3 : s4;
    __half* dst = (sel == 0) ? hsH : (wH + (size_t)(sel - 1) * n);
    float4 v = *(const float4*)(src + i);
    ((__half2*)(dst + i))[0] = __floats2half2_rn(v.x, v.y);
    ((__half2*)(dst + i))[1] = __floats2half2_rn(v.z, v.w);
}

// ============================================================
// Fused QKV GEMM: z=0 -> Q (fp32, per-head), z=1 -> K (fp32,
// per-head), z=2 -> V (*lv, fp16, per-head).
// CTA tile 128x128, 256 thr, K-stage 64, double-buffered.
// ============================================================
#define PITCH 144
#define MATSZ (128 * PITCH)      // 18432
#define STAGESZ (2 * MATSZ)      // 36864
#define GSMEM (2 * STAGESZ)      // 73728

template <int BODY>
__device__ __forceinline__ void gemm_body(
    const __half* pA, const __half* pB, uint32_t sb,
    int t, int lane, int mw, int nw, float acc[2][8][4])
{
#define LOAD_STAGE(sidx, k0) do {                                            \
        uint32_t base = sb + ((sidx) & 1) * STAGESZ;                         \
        _Pragma("unroll")                                                    \
        for (int mat = 0; mat < 2; mat++) {                                  \
            const __half* g = mat ? pB : pA;                                 \
            _Pragma("unroll")                                                \
            for (int r = 0; r < 4; r++) {                                    \
                int idx = t + 256 * r;                                       \
                int row = idx >> 3, c = idx & 7;                             \
                CPASYNC16(base + mat * MATSZ + row * PITCH + c * 16,         \
                          g + (size_t)row * 2048 + (k0) + c * 8);            \
            }                                                                \
        }                                                                    \
        CP_COMMIT();                                                         \
    } while (0)

    LOAD_STAGE(0, 0);
    for (int s = 0; s < 32; s++) {
        if (s < 31) { LOAD_STAGE(s + 1, (s + 1) * 64); CP_WAIT(1); }
        else        { CP_WAIT(0); }
        __syncthreads();
        const uint32_t base = sb + (s & 1) * STAGESZ;
        const uint32_t aB = base;
        const uint32_t bB = base + MATSZ;
#pragma unroll
        for (int ks = 0; ks < 4; ks++) {
            uint32_t a_hi[2][4], b_hi[8][2];
#pragma unroll
            for (int mt = 0; mt < 2; mt++) {
                int row = mw + mt * 16 + (lane & 15);
                int chunk = 2 * ks + (lane >> 4);
                ldsm4(a_hi[mt], aB + row * PITCH + chunk * 16);
            }
#pragma unroll
            for (int j = 0; j < 4; j++) {
                int row = nw + j * 16 + ((lane >> 4) << 3) + (lane & 7);
                int chunk = 2 * ks + ((lane >> 3) & 1);
                uint32_t rh[4];
                ldsm4(rh, bB + row * PITCH + chunk * 16);
                b_hi[2 * j][0] = rh[0]; b_hi[2 * j][1] = rh[1];
                b_hi[2 * j + 1][0] = rh[2]; b_hi[2 * j + 1][1] = rh[3];
            }
#pragma unroll
            for (int mt = 0; mt < 2; mt++)
#pragma unroll
                for (int nt = 0; nt < 8; nt++)
                    mma16816(acc[mt][nt], a_hi[mt], b_hi[nt]);
        }
        __syncthreads();
    }
#undef LOAD_STAGE
}

__global__ __launch_bounds__(256) void gemm_qkv_kernel(
    const __half* __restrict__ Ahi, const __half* __restrict__ Wall,
    float* __restrict__ Q, float* __restrict__ K,
    __half* __restrict__ Vh, const float* __restrict__ lv)
{
    extern __shared__ char smem[];
    const uint32_t sb = smem_u32(smem);
    const int t = threadIdx.x;
    const int lane = t & 31;
    const int w = t >> 5;
    const int mw = (w >> 1) * 32;
    const int nw = (w & 1) * 64;
    const int mbase = blockIdx.y * 128;
    const int nbase = blockIdx.x * 128;
    const int z = blockIdx.z;

    const __half* pA = Ahi + (size_t)mbase * 2048;
    const __half* pB = Wall + (size_t)z * (2048 * 2048) + (size_t)nbase * 2048;

    float acc[2][8][4];
#pragma unroll
    for (int i = 0; i < 2; i++)
#pragma unroll
        for (int j = 0; j < 8; j++)
#pragma unroll
            for (int k = 0; k < 4; k++) acc[i][j][k] = 0.f;

    gemm_body<0>(pA, pB, sb, t, lane, mw, nw, acc);

    float* C = (z == 0) ? Q : K;
#pragma unroll
    for (int mt = 0; mt < 2; mt++)
#pragma unroll
        for (int nt = 0; nt < 8; nt++) {
            const float* a = acc[mt][nt];
            int r0 = mbase + mw + mt * 16 + (lane >> 2);
            int n  = nbase + nw + nt * 8 + 2 * (lane & 3);
            size_t o0 = ((size_t)(n >> 7) * 2048 + r0) * 128 + (n & 127);
            size_t o1 = ((size_t)(n >> 7) * 2048 + r0 + 8) * 128 + (n & 127);
            if (z == 2) {
                float s0 = lv[n], s1 = lv[n + 1];
                *(__half2*)&Vh[o0] = __floats2half2_rn(a[0] * s0, a[1] * s1);
                *(__half2*)&Vh[o1] = __floats2half2_rn(a[2] * s0, a[3] * s1);
            } else {
                *(float2*)&C[o0] = make_float2(a[0], a[1]);
                *(float2*)&C[o1] = make_float2(a[2], a[3]);
            }
        }
}

__global__ __launch_bounds__(256) void gemm_out_kernel(
    const __half* __restrict__ Ahi, const __half* __restrict__ Bhi,
    float* __restrict__ C)
{
    extern __shared__ char smem[];
    const uint32_t sb = smem_u32(smem);
    const int t = threadIdx.x;
    const int lane = t & 31;
    const int w = t >> 5;
    const int mw = (w >> 1) * 32;
    const int nw = (w & 1) * 64;
    const int mbase = blockIdx.y * 128;
    const int nbase = blockIdx.x * 128;

    const __half* pA = Ahi + (size_t)mbase * 2048;
    const __half* pB = Bhi + (size_t)nbase * 2048;

    float acc[2][8][4];
#pragma unroll
    for (int i = 0; i < 2; i++)
#pragma unroll
        for (int j = 0; j < 8; j++)
#pragma unroll
            for (int k = 0; k < 4; k++) acc[i][j][k] = 0.f;

    gemm_body<1>(pA, pB, sb, t, lane, mw, nw, acc);

#pragma unroll
    for (int mt = 0; mt < 2; mt++)
#pragma unroll
        for (int nt = 0; nt < 8; nt++) {
            const float* a = acc[mt][nt];
            int r0 = mbase + mw + mt * 16 + (lane >> 2);
            int n  = nbase + nw + nt * 8 + 2 * (lane & 3);
            *(float2*)(C + (size_t)r0 * 2048 + n)       = make_float2(a[0], a[1]);
            *(float2*)(C + (size_t)(r0 + 8) * 2048 + n) = make_float2(a[2], a[3]);
        }
}

// ============================================================
// RoPE + IA3(q) + scale; emits fp16 q, k.
// ============================================================
__global__ __launch_bounds__(128) void rope_conv_kernel(
    const float* __restrict__ Qm, const float* __restrict__ Km,
    const float* __restrict__ cosT, const float* __restrict__ sinT,
    const float* __restrict__ lk,
    __half* __restrict__ qh, __half* __restrict__ kh)
{
    const int s = blockIdx.x;
    const int h = blockIdx.y;
    const int d = threadIdx.x;
    const float scale = 0.08838834764831845f;   // 1/sqrt(128)
    size_t rb = ((size_t)h * S + s) * HD;
    float c  = cosT[s * HD + d];
    float sn = sinT[s * HD + d];
    int   p  = d ^ 64;
    float sign = (d < 64) ? -1.f : 1.f;
    float q = (Qm[rb + d] * c + sign * Qm[rb + p] * sn) * lk[h * HD + d] * scale;
    float k = Km[rb + d] * c + sign * Km[rb + p] * sn;
    qh[rb + d] = __float2half_rn(q);
    kh[rb + d] = __float2half_rn(k);
}

// ============================================================
// Causal flash attention, mma.sync 1-term fp16. (R10, unchanged)
// ============================================================
#define FPB 272
#define QMAT (128 * FPB)
#define KVMAT (64 * FPB)

__global__ __launch_bounds__(256) void flash_mma_kernel(
    const __half* __restrict__ Qh_, const __half* __restrict__ Kh_,
    const __half* __restrict__ Vh_, __half* __restrict__ OH)
{
    extern __shared__ char smem[];
    const uint32_t sb = smem_u32(smem);
    const int t = threadIdx.x, lane = t & 31, w = t >> 5;
    const int qt = 15 - (int)blockIdx.x;
    const int h = blockIdx.y;
    const int mw = w * 16;
    const size_t hoff = (size_t)h * S * HD;
    const __half* Qhp = Qh_ + hoff + (size_t)qt * 128 * HD;
    const __half* Khp = Kh_ + hoff;
    const __half* Vhp = Vh_ + hoff;

    const uint32_t qB  = sb;
    const uint32_t kvB = sb + QMAT;

#pragma unroll
    for (int r = 0; r < 8; r++) {
        int idx = t + 256 * r;
        int row = idx >> 4, c = idx & 15;
        CPASYNC16(qB + row * FPB + c * 16, Qhp + row * 128 + c * 8);
    }
    CP_COMMIT();

#define LOADKV(kt_, p_) do {                                                  \
        uint32_t b_ = kvB + (p_) * (2 * KVMAT);                               \
        const __half* g0 = Khp + (size_t)(kt_) * 64 * 128;                    \
        const __half* g1 = Vhp + (size_t)(kt_) * 64 * 128;                    \
        _Pragma("unroll")                                                     \
        for (int r_ = 0; r_ < 4; r_++) {                                      \
            int idx_ = t + 256 * r_;                                          \
            int row_ = idx_ >> 4, c_ = idx_ & 15;                             \
            uint32_t so_ = row_ * FPB + c_ * 16;                              \
            uint32_t go_ = row_ * 128 + c_ * 8;                               \
            CPASYNC16(b_ + so_,         g0 + go_);                            \
            CPASYNC16(b_ + KVMAT + so_, g1 + go_);                            \
        }                                                                     \
        CP_COMMIT();                                                          \
    } while (0)

    float acc[16][4];
#pragma unroll
    for (int i = 0; i < 16; i++)
#pragma unroll
        for (int j = 0; j < 4; j++) acc[i][j] = 0.f;
    float m0 = -1e30f, m1 = -1e30f, l0 = 0.f, l1 = 0.f;

    const int ktmax = 2 * qt + 1;
    LOADKV(0, 0);

    for (int kt = 0; kt <= ktmax; kt++) {
        if (kt < ktmax) { LOADKV(kt + 1, (kt + 1) & 1); CP_WAIT(1); }
        else            { CP_WAIT(0); }
        __syncthreads();
        const uint32_t base = kvB + (kt & 1) * (2 * KVMAT);

        float s[8][4];
#pragma unroll
        for (int i = 0; i < 8; i++)
#pragma unroll
            for (int j = 0; j < 4; j++) s[i][j] = 0.f;
#pragma unroll
        for (int kc = 0; kc < 8; kc++) {
            uint32_t aH[4];
            ldsm4(aH, qB + (mw + (lane & 15)) * FPB + (2 * kc + (lane >> 4)) * 16);
            uint32_t bH[8][2];
#pragma unroll
            for (int j = 0; j < 4; j++) {
                int row = j * 16 + ((lane >> 4) << 3) + (lane & 7);
                uint32_t rh[4];
                ldsm4(rh, base + row * FPB + (2 * kc + ((lane >> 3) & 1)) * 16);
                bH[2 * j][0] = rh[0]; bH[2 * j][1] = rh[1];
                bH[2 * j + 1][0] = rh[2]; bH[2 * j + 1][1] = rh[3];
            }
#pragma unroll
            for (int nb = 0; nb < 8; nb++)
                mma16816(s[nb], aH, bH[nb]);
        }

        const int qrow = qt * 128 + mw + (lane >> 2);
        if (kt * 64 + 63 > qt * 128 + mw) {
#pragma unroll
            for (int nb = 0; nb < 8; nb++) {
                int col = kt * 64 + 8 * nb + 2 * (lane & 3);
                if (col     > qrow)     s[nb][0] = -1e30f;
                if (col + 1 > qrow)     s[nb][1] = -1e30f;
                if (col     > qrow + 8) s[nb][2] = -1e30f;
                if (col + 1 > qrow + 8) s[nb][3] = -1e30f;
            }
        }

        float mx0 = -1e30f, mx1 = -1e30f;
#pragma unroll
        for (int nb = 0; nb < 8; nb++) {
            mx0 = fmaxf(mx0, fmaxf(s[nb][0], s[nb][1]));
            mx1 = fmaxf(mx1, fmaxf(s[nb][2], s[nb][3]));
        }
        mx0 = fmaxf(mx0, __shfl_xor_sync(0xffffffffu, mx0, 1));
        mx0 = fmaxf(mx0, __shfl_xor_sync(0xffffffffu, mx0, 2));
        mx1 = fmaxf(mx1, __shfl_xor_sync(0xffffffffu, mx1, 1));
        mx1 = fmaxf(mx1, __shfl_xor_sync(0xffffffffu, mx1, 2));
        float mn0 = fmaxf(m0, mx0), mn1 = fmaxf(m1, mx1);
        float al0 = __expf(m0 - mn0), al1 = __expf(m1 - mn1);
        m0 = mn0; m1 = mn1;

        float sum0 = 0.f, sum1 = 0.f;
        uint32_t ph0[8], ph1[8];
#pragma unroll
        for (int nb = 0; nb < 8; nb++) {
            float p0 = __expf(s[nb][0] - mn0), p1 = __expf(s[nb][1] - mn0);
            float p2 = __expf(s[nb][2] - mn1), p3 = __expf(s[nb][3] - mn1);
            sum0 += p0 + p1; sum1 += p2 + p3;
            __half2 h01 = __floats2half2_rn(p0, p1);
            __half2 h23 = __floats2half2_rn(p2, p3);
            ph0[nb] = *(uint32_t*)&h01;
            ph1[nb] = *(uint32_t*)&h23;
        }
        sum0 += __shfl_xor_sync(0xffffffffu, sum0, 1);
        sum0 += __shfl_xor_sync(0xffffffffu, sum0, 2);
        sum1 += __shfl_xor_sync(0xffffffffu, sum1, 1);
        sum1 += __shfl_xor_sync(0xffffffffu, sum1, 2);
        l0 = l0 * al0 + sum0;
        l1 = l1 * al1 + sum1;
#pragma unroll
        for (int nb = 0; nb < 16; nb++) {
            acc[nb][0] *= al0; acc[nb][1] *= al0;
            acc[nb][2] *= al1; acc[nb][3] *= al1;
        }

#pragma unroll
        for (int kc = 0; kc < 4; kc++) {
            uint32_t paH[4] = {ph0[2 * kc], ph1[2 * kc], ph0[2 * kc + 1], ph1[2 * kc + 1]};
#pragma unroll
            for (int nb2 = 0; nb2 < 8; nb2++) {
                uint32_t vaddr = base + KVMAT +
                                 (kc * 16 + (lane & 15)) * FPB + (2 * nb2 + (lane >> 4)) * 16;
                uint32_t vh[4];
                ldsm4t(vh, vaddr);
                uint32_t bh0[2] = {vh[0], vh[1]}, bh1[2] = {vh[2], vh[3]};
                mma16816(acc[2 * nb2], paH, bh0);
                mma16816(acc[2 * nb2 + 1], paH, bh1);
            }
        }
        __syncthreads();
    }

    float inv0 = 1.f / l0, inv1 = 1.f / l1;
    int r = qt * 128 + mw + (lane >> 2);
#pragma unroll
    for (int nb = 0; nb < 16; nb++) {
        int col = h * 128 + 8 * nb + 2 * (lane & 3);
        *(__half2*)&OH[(size_t)r * D + col] =
            __floats2half2_rn(acc[nb][0] * inv0, acc[nb][1] * inv0);
        *(__half2*)&OH[(size_t)(r + 8) * D + col] =
            __floats2half2_rn(acc[nb][2] * inv1, acc[nb][3] * inv1);
    }
}

// ============================================================
extern "C" void kernel_launch(void* const* d_in, const int* in_sizes, int n_in,
                              void* d_out, int out_size)
{
    const float* hs   = (const float*)d_in[0];
    const float* cosT = (const float*)d_in[2];
    const float* sinT = (const float*)d_in[3];
    const float* Wq   = (const float*)d_in[4];
    const float* Wk   = (const float*)d_in[5];
    const float* Wv   = (const float*)d_in[6];
    const float* Wo   = (const float*)d_in[7];
    const float* lk   = (const float*)d_in[8];
    const float* lv   = (const float*)d_in[9];
    float* out = (float*)d_out;
    (void)in_sizes; (void)n_in; (void)out_size;

    float *q, *k;
    cudaGetSymbolAddress((void**)&q, g_q);
    cudaGetSymbolAddress((void**)&k, g_k);
    __half *hsH, *wH, *oH, *qh, *kh, *vh;
    cudaGetSymbolAddress((void**)&hsH, g_hs_hi);
    cudaGetSymbolAddress((void**)&wH, g_w_hi);
    cudaGetSymbolAddress((void**)&oH, g_o_hi);
    cudaGetSymbolAddress((void**)&qh, g_qh);
    cudaGetSymbolAddress((void**)&kh, g_kh);
    cudaGetSymbolAddress((void**)&vh, g_vh);

    const int n = S * D;
    // all 5 converts in one launch: 5 tensors x n/4 threads
    conv5_kernel<<<5 * (n / 4) / 256, 256>>>(hs, Wq, Wk, Wv, Wo, hsH, wH, n);

    cudaFuncSetAttribute(gemm_qkv_kernel,
                         cudaFuncAttributeMaxDynamicSharedMemorySize, GSMEM);
    cudaFuncSetAttribute(gemm_out_kernel,
                         cudaFuncAttributeMaxDynamicSharedMemorySize, GSMEM);

    gemm_qkv_kernel<<<dim3(D / 128, S / 128, 3), 256, GSMEM>>>(
        hsH, wH, q, k, vh, lv);

    rope_conv_kernel<<<dim3(S, H), 128>>>(q, k, cosT, sinT, lk, qh, kh);

    int fsmem = QMAT + 2 * 2 * KVMAT;   // 104448
    cudaFuncSetAttribute(flash_mma_kernel,
                         cudaFuncAttributeMaxDynamicSharedMemorySize, fsmem);
    flash_mma_kernel<<<dim3(16, 16), 256, fsmem>>>(qh, kh, vh, oH);

    gemm_out_kernel<<<dim3(D / 128, S / 128), 256, GSMEM>>>(
        oH, wH + 3 * (size_t)n, out);
}

// round 12
// speedup vs baseline: 2.6029x; 1.1322x over previous
#include <cuda_runtime.h>
#include <cuda_fp16.h>
#include <cstdint>
#include <math.h>

#define S 2048
#define D 2048
#define H 16
#define HD 128

// ---- scratch (allocation-free rule: __device__ globals) ----
__device__ float g_q[H * S * HD];
__device__ float g_k[H * S * HD];
__device__ __half g_hs_hi[S * D];
__device__ __half g_w_hi[4][D * D];
__device__ __half g_o_hi[S * D];
__device__ __half g_qh[H * S * HD];
__device__ __half g_kh[H * S * HD];
__device__ __half g_vh[H * S * HD];

// ============================================================
// helpers (arch-agnostic: mma.sync / ldmatrix / cp.async)
// ============================================================
__device__ __forceinline__ uint32_t smem_u32(const void* p) {
    uint32_t a;
    asm("{ .reg .u64 t; cvta.to.shared.u64 t, %1; cvt.u32.u64 %0, t; }"
        : "=r"(a) : "l"(p));
    return a;
}
__device__ __forceinline__ void mma16816(float* c, const uint32_t* a,
                                         const uint32_t* b) {
    asm volatile(
        "mma.sync.aligned.m16n8k16.row.col.f32.f16.f16.f32 "
        "{%0,%1,%2,%3}, {%4,%5,%6,%7}, {%8,%9}, {%0,%1,%2,%3};"
        : "+f"(c[0]), "+f"(c[1]), "+f"(c[2]), "+f"(c[3])
        : "r"(a[0]), "r"(a[1]), "r"(a[2]), "r"(a[3]), "r"(b[0]), "r"(b[1]));
}
__device__ __forceinline__ void ldsm4(uint32_t* r, uint32_t addr) {
    asm volatile("ldmatrix.sync.aligned.m8n8.x4.shared.b16 {%0,%1,%2,%3}, [%4];"
                 : "=r"(r[0]), "=r"(r[1]), "=r"(r[2]), "=r"(r[3]) : "r"(addr));
}
__device__ __forceinline__ void ldsm4t(uint32_t* r, uint32_t addr) {
    asm volatile("ldmatrix.sync.aligned.m8n8.x4.trans.shared.b16 {%0,%1,%2,%3}, [%4];"
                 : "=r"(r[0]), "=r"(r[1]), "=r"(r[2]), "=r"(r[3]) : "r"(addr));
}
#define CPASYNC16(sa, ga) \
    asm volatile("cp.async.cg.shared.global [%0], [%1], 16;" \
                 :: "r"(sa), "l"(ga) : "memory")
#define CP_COMMIT() asm volatile("cp.async.commit_group;" ::: "memory")
#define CP_WAIT(N)  asm volatile("cp.async.wait_group %0;" :: "n"(N) : "memory")

// ============================================================
// fused fp32 -> fp16 convert for 5 tensors (hs + 4 weights)
// ============================================================
__global__ __launch_bounds__(256) void conv5_kernel(
    const float* __restrict__ s0, const float* __restrict__ s1,
    const float* __restrict__ s2, const float* __restrict__ s3,
    const float* __restrict__ s4,
    __half* __restrict__ hsH, __half* __restrict__ wH, int n)
{
    int gi = blockIdx.x * 256 + threadIdx.x;
    int per = n / 4;                 // threads per tensor
    int sel = gi / per;
    int i = (gi - sel * per) * 4;
    const float* src = (sel == 0) ? s0 : (sel == 1) ? s1 :
                       (sel == 2) ? s2 : (sel == 3) ? s3 : s4;
    __half* dst = (sel == 0) ? hsH : (wH + (size_t)(sel - 1) * n);
    float4 v = *(const float4*)(src + i);
    ((__half2*)(dst + i))[0] = __floats2half2_rn(v.x, v.y);
    ((__half2*)(dst + i))[1] = __floats2half2_rn(v.z, v.w);
}

// ============================================================
// Fused QKV GEMM: z=0 -> Q (fp32), z=1 -> K (fp32),
// z=2 -> V (*lv, fp16). CTA tile 128x128, K-stage 64.
// ============================================================
#define PITCH 144
#define MATSZ (128 * PITCH)      // 18432
#define STAGESZ (2 * MATSZ)      // 36864
#define GSMEM (2 * STAGESZ)      // 73728

template <int BODY>
__device__ __forceinline__ void gemm_body(
    const __half* pA, const __half* pB, uint32_t sb,
    int t, int lane, int mw, int nw, float acc[2][8][4])
{
#define LOAD_STAGE(sidx, k0) do {                                            \
        uint32_t base = sb + ((sidx) & 1) * STAGESZ;                         \
        _Pragma("unroll")                                                    \
        for (int mat = 0; mat < 2; mat++) {                                  \
            const __half* g = mat ? pB : pA;                                 \
            _Pragma("unroll")                                                \
            for (int r = 0; r < 4; r++) {                                    \
                int idx = t + 256 * r;                                       \
                int row = idx >> 3, c = idx & 7;                             \
                CPASYNC16(base + mat * MATSZ + row * PITCH + c * 16,         \
                          g + (size_t)row * 2048 + (k0) + c * 8);            \
            }                                                                \
        }                                                                    \
        CP_COMMIT();                                                         \
    } while (0)

    LOAD_STAGE(0, 0);
    for (int s = 0; s < 32; s++) {
        if (s < 31) { LOAD_STAGE(s + 1, (s + 1) * 64); CP_WAIT(1); }
        else        { CP_WAIT(0); }
        __syncthreads();
        const uint32_t base = sb + (s & 1) * STAGESZ;
        const uint32_t aB = base;
        const uint32_t bB = base + MATSZ;
#pragma unroll
        for (int ks = 0; ks < 4; ks++) {
            uint32_t a_hi[2][4], b_hi[8][2];
#pragma unroll
            for (int mt = 0; mt < 2; mt++) {
                int row = mw + mt * 16 + (lane & 15);
                int chunk = 2 * ks + (lane >> 4);
                ldsm4(a_hi[mt], aB + row * PITCH + chunk * 16);
            }
#pragma unroll
            for (int j = 0; j < 4; j++) {
                int row = nw + j * 16 + ((lane >> 4) << 3) + (lane & 7);
                int chunk = 2 * ks + ((lane >> 3) & 1);
                uint32_t rh[4];
                ldsm4(rh, bB + row * PITCH + chunk * 16);
                b_hi[2 * j][0] = rh[0]; b_hi[2 * j][1] = rh[1];
                b_hi[2 * j + 1][0] = rh[2]; b_hi[2 * j + 1][1] = rh[3];
            }
#pragma unroll
            for (int mt = 0; mt < 2; mt++)
#pragma unroll
                for (int nt = 0; nt < 8; nt++)
                    mma16816(acc[mt][nt], a_hi[mt], b_hi[nt]);
        }
        __syncthreads();
    }
#undef LOAD_STAGE
}

__global__ __launch_bounds__(256) void gemm_qkv_kernel(
    const __half* __restrict__ Ahi, const __half* __restrict__ Wall,
    float* __restrict__ Q, float* __restrict__ K,
    __half* __restrict__ Vh, const float* __restrict__ lv)
{
    extern __shared__ char smem[];
    const uint32_t sb = smem_u32(smem);
    const int t = threadIdx.x;
    const int lane = t & 31;
    const int w = t >> 5;
    const int mw = (w >> 1) * 32;
    const int nw = (w & 1) * 64;
    const int mbase = blockIdx.y * 128;
    const int nbase = blockIdx.x * 128;
    const int z = blockIdx.z;

    const __half* pA = Ahi + (size_t)mbase * 2048;
    const __half* pB = Wall + (size_t)z * (2048 * 2048) + (size_t)nbase * 2048;

    float acc[2][8][4];
#pragma unroll
    for (int i = 0; i < 2; i++)
#pragma unroll
        for (int j = 0; j < 8; j++)
#pragma unroll
            for (int k = 0; k < 4; k++) acc[i][j][k] = 0.f;

    gemm_body<0>(pA, pB, sb, t, lane, mw, nw, acc);

    float* C = (z == 0) ? Q : K;
#pragma unroll
    for (int mt = 0; mt < 2; mt++)
#pragma unroll
        for (int nt = 0; nt < 8; nt++) {
            const float* a = acc[mt][nt];
            int r0 = mbase + mw + mt * 16 + (lane >> 2);
            int n  = nbase + nw + nt * 8 + 2 * (lane & 3);
            size_t o0 = ((size_t)(n >> 7) * 2048 + r0) * 128 + (n & 127);
            size_t o1 = ((size_t)(n >> 7) * 2048 + r0 + 8) * 128 + (n & 127);
            if (z == 2) {
                float s0 = lv[n], s1 = lv[n + 1];
                *(__half2*)&Vh[o0] = __floats2half2_rn(a[0] * s0, a[1] * s1);
                *(__half2*)&Vh[o1] = __floats2half2_rn(a[2] * s0, a[3] * s1);
            } else {
                *(float2*)&C[o0] = make_float2(a[0], a[1]);
                *(float2*)&C[o1] = make_float2(a[2], a[3]);
            }
        }
}

__global__ __launch_bounds__(256) void gemm_out_kernel(
    const __half* __restrict__ Ahi, const __half* __restrict__ Bhi,
    float* __restrict__ C)
{
    extern __shared__ char smem[];
    const uint32_t sb = smem_u32(smem);
    const int t = threadIdx.x;
    const int lane = t & 31;
    const int w = t >> 5;
    const int mw = (w >> 1) * 32;
    const int nw = (w & 1) * 64;
    const int mbase = blockIdx.y * 128;
    const int nbase = blockIdx.x * 128;

    const __half* pA = Ahi + (size_t)mbase * 2048;
    const __half* pB = Bhi + (size_t)nbase * 2048;

    float acc[2][8][4];
#pragma unroll
    for (int i = 0; i < 2; i++)
#pragma unroll
        for (int j = 0; j < 8; j++)
#pragma unroll
            for (int k = 0; k < 4; k++) acc[i][j][k] = 0.f;

    gemm_body<1>(pA, pB, sb, t, lane, mw, nw, acc);

#pragma unroll
    for (int mt = 0; mt < 2; mt++)
#pragma unroll
        for (int nt = 0; nt < 8; nt++) {
            const float* a = acc[mt][nt];
            int r0 = mbase + mw + mt * 16 + (lane >> 2);
            int n  = nbase + nw + nt * 8 + 2 * (lane & 3);
            *(float2*)(C + (size_t)r0 * 2048 + n)       = make_float2(a[0], a[1]);
            *(float2*)(C + (size_t)(r0 + 8) * 2048 + n) = make_float2(a[2], a[3]);
        }
}

// ============================================================
// RoPE + IA3(q) + scale; emits fp16 q, k.
// ============================================================
__global__ __launch_bounds__(128) void rope_conv_kernel(
    const float* __restrict__ Qm, const float* __restrict__ Km,
    const float* __restrict__ cosT, const float* __restrict__ sinT,
    const float* __restrict__ lk,
    __half* __restrict__ qh, __half* __restrict__ kh)
{
    const int s = blockIdx.x;
    const int h = blockIdx.y;
    const int d = threadIdx.x;
    const float scale = 0.08838834764831845f;   // 1/sqrt(128)
    size_t rb = ((size_t)h * S + s) * HD;
    float c  = cosT[s * HD + d];
    float sn = sinT[s * HD + d];
    int   p  = d ^ 64;
    float sign = (d < 64) ? -1.f : 1.f;
    float q = (Qm[rb + d] * c + sign * Qm[rb + p] * sn) * lk[h * HD + d] * scale;
    float k = Km[rb + d] * c + sign * Km[rb + p] * sn;
    qh[rb + d] = __float2half_rn(q);
    kh[rb + d] = __float2half_rn(k);
}

// ============================================================
// Causal flash attention, mma.sync fp16, TRIANGLE-PAIRED:
// each CTA processes q-tiles {15-j, j} (34 kt-iters, balanced).
// Grid = 8 x 16 = 128 CTAs = one wave.
// ============================================================
#define FPB 272
#define QMAT (128 * FPB)
#define KVMAT (64 * FPB)

__global__ __launch_bounds__(256) void flash_mma_kernel(
    const __half* __restrict__ Qh_, const __half* __restrict__ Kh_,
    const __half* __restrict__ Vh_, __half* __restrict__ OH)
{
    extern __shared__ char smem[];
    const uint32_t sb = smem_u32(smem);
    const int t = threadIdx.x, lane = t & 31, w = t >> 5;
    const int j = blockIdx.x;            // 0..7
    const int h = blockIdx.y;
    const int mw = w * 16;
    const size_t hoff = (size_t)h * S * HD;
    const __half* Khp = Kh_ + hoff;
    const __half* Vhp = Vh_ + hoff;

    const uint32_t qB  = sb;
    const uint32_t kvB = sb + QMAT;

#define LOADKV(kt_, p_) do {                                                  \
        uint32_t b_ = kvB + (p_) * (2 * KVMAT);                               \
        const __half* g0 = Khp + (size_t)(kt_) * 64 * 128;                    \
        const __half* g1 = Vhp + (size_t)(kt_) * 64 * 128;                    \
        _Pragma("unroll")                                                     \
        for (int r_ = 0; r_ < 4; r_++) {                                      \
            int idx_ = t + 256 * r_;                                          \
            int row_ = idx_ >> 4, c_ = idx_ & 15;                             \
            uint32_t so_ = row_ * FPB + c_ * 16;                              \
            uint32_t go_ = row_ * 128 + c_ * 8;                               \
            CPASYNC16(b_ + so_,         g0 + go_);                            \
            CPASYNC16(b_ + KVMAT + so_, g1 + go_);                            \
        }                                                                     \
        CP_COMMIT();                                                          \
    } while (0)

    for (int sub = 0; sub < 2; sub++) {
        const int qt = sub ? j : (15 - j);          // big tile first
        const __half* Qhp = Qh_ + hoff + (size_t)qt * 128 * HD;

        // Q tile load (qB free: prior subtile's reads fenced by loop syncs)
#pragma unroll
        for (int r = 0; r < 8; r++) {
            int idx = t + 256 * r;
            int row = idx >> 4, c = idx & 15;
            CPASYNC16(qB + row * FPB + c * 16, Qhp + row * 128 + c * 8);
        }
        CP_COMMIT();

        float acc[16][4];
#pragma unroll
        for (int i = 0; i < 16; i++)
#pragma unroll
            for (int jj = 0; jj < 4; jj++) acc[i][jj] = 0.f;
        float m0 = -1e30f, m1 = -1e30f, l0 = 0.f, l1 = 0.f;

        const int ktmax = 2 * qt + 1;
        LOADKV(0, 0);

        for (int kt = 0; kt <= ktmax; kt++) {
            if (kt < ktmax) { LOADKV(kt + 1, (kt + 1) & 1); CP_WAIT(1); }
            else            { CP_WAIT(0); }
            __syncthreads();
            const uint32_t base = kvB + (kt & 1) * (2 * KVMAT);

            // ---- S = Qh @ Kh^T ----
            float s[8][4];
#pragma unroll
            for (int i = 0; i < 8; i++)
#pragma unroll
                for (int jj = 0; jj < 4; jj++) s[i][jj] = 0.f;
#pragma unroll
            for (int kc = 0; kc < 8; kc++) {
                uint32_t aH[4];
                ldsm4(aH, qB + (mw + (lane & 15)) * FPB + (2 * kc + (lane >> 4)) * 16);
                uint32_t bH[8][2];
#pragma unroll
                for (int jj = 0; jj < 4; jj++) {
                    int row = jj * 16 + ((lane >> 4) << 3) + (lane & 7);
                    uint32_t rh[4];
                    ldsm4(rh, base + row * FPB + (2 * kc + ((lane >> 3) & 1)) * 16);
                    bH[2 * jj][0] = rh[0]; bH[2 * jj][1] = rh[1];
                    bH[2 * jj + 1][0] = rh[2]; bH[2 * jj + 1][1] = rh[3];
                }
#pragma unroll
                for (int nb = 0; nb < 8; nb++)
                    mma16816(s[nb], aH, bH[nb]);
            }

            const int qrow = qt * 128 + mw + (lane >> 2);
            if (kt * 64 + 63 > qt * 128 + mw) {
#pragma unroll
                for (int nb = 0; nb < 8; nb++) {
                    int col = kt * 64 + 8 * nb + 2 * (lane & 3);
                    if (col     > qrow)     s[nb][0] = -1e30f;
                    if (col + 1 > qrow)     s[nb][1] = -1e30f;
                    if (col     > qrow + 8) s[nb][2] = -1e30f;
                    if (col + 1 > qrow + 8) s[nb][3] = -1e30f;
                }
            }

            float mx0 = -1e30f, mx1 = -1e30f;
#pragma unroll
            for (int nb = 0; nb < 8; nb++) {
                mx0 = fmaxf(mx0, fmaxf(s[nb][0], s[nb][1]));
                mx1 = fmaxf(mx1, fmaxf(s[nb][2], s[nb][3]));
            }
            mx0 = fmaxf(mx0, __shfl_xor_sync(0xffffffffu, mx0, 1));
            mx0 = fmaxf(mx0, __shfl_xor_sync(0xffffffffu, mx0, 2));
            mx1 = fmaxf(mx1, __shfl_xor_sync(0xffffffffu, mx1, 1));
            mx1 = fmaxf(mx1, __shfl_xor_sync(0xffffffffu, mx1, 2));
            float mn0 = fmaxf(m0, mx0), mn1 = fmaxf(m1, mx1);
            float al0 = __expf(m0 - mn0), al1 = __expf(m1 - mn1);
            m0 = mn0; m1 = mn1;

            float sum0 = 0.f, sum1 = 0.f;
            uint32_t ph0[8], ph1[8];
#pragma unroll
            for (int nb = 0; nb < 8; nb++) {
                float p0 = __expf(s[nb][0] - mn0), p1 = __expf(s[nb][1] - mn0);
                float p2 = __expf(s[nb][2] - mn1), p3 = __expf(s[nb][3] - mn1);
                sum0 += p0 + p1; sum1 += p2 + p3;
                __half2 h01 = __floats2half2_rn(p0, p1);
                __half2 h23 = __floats2half2_rn(p2, p3);
                ph0[nb] = *(uint32_t*)&h01;
                ph1[nb] = *(uint32_t*)&h23;
            }
            sum0 += __shfl_xor_sync(0xffffffffu, sum0, 1);
            sum0 += __shfl_xor_sync(0xffffffffu, sum0, 2);
            sum1 += __shfl_xor_sync(0xffffffffu, sum1, 1);
            sum1 += __shfl_xor_sync(0xffffffffu, sum1, 2);
            l0 = l0 * al0 + sum0;
            l1 = l1 * al1 + sum1;
#pragma unroll
            for (int nb = 0; nb < 16; nb++) {
                acc[nb][0] *= al0; acc[nb][1] *= al0;
                acc[nb][2] *= al1; acc[nb][3] *= al1;
            }

            // ---- O += Ph @ Vh ----
#pragma unroll
            for (int kc = 0; kc < 4; kc++) {
                uint32_t paH[4] = {ph0[2 * kc], ph1[2 * kc],
                                   ph0[2 * kc + 1], ph1[2 * kc + 1]};
#pragma unroll
                for (int nb2 = 0; nb2 < 8; nb2++) {
                    uint32_t vaddr = base + KVMAT +
                                     (kc * 16 + (lane & 15)) * FPB +
                                     (2 * nb2 + (lane >> 4)) * 16;
                    uint32_t vh[4];
                    ldsm4t(vh, vaddr);
                    uint32_t bh0[2] = {vh[0], vh[1]}, bh1[2] = {vh[2], vh[3]};
                    mma16816(acc[2 * nb2], paH, bh0);
                    mma16816(acc[2 * nb2 + 1], paH, bh1);
                }
            }
            __syncthreads();
        }

        // ---- epilogue: normalize, round to fp16, write ----
        float inv0 = 1.f / l0, inv1 = 1.f / l1;
        int r = qt * 128 + mw + (lane >> 2);
#pragma unroll
        for (int nb = 0; nb < 16; nb++) {
            int col = h * 128 + 8 * nb + 2 * (lane & 3);
            *(__half2*)&OH[(size_t)r * D + col] =
                __floats2half2_rn(acc[nb][0] * inv0, acc[nb][1] * inv0);
            *(__half2*)&OH[(size_t)(r + 8) * D + col] =
                __floats2half2_rn(acc[nb][2] * inv1, acc[nb][3] * inv1);
        }
    }
}

// ============================================================
extern "C" void kernel_launch(void* const* d_in, const int* in_sizes, int n_in,
                              void* d_out, int out_size)
{
    const float* hs   = (const float*)d_in[0];
    const float* cosT = (const float*)d_in[2];
    const float* sinT = (const float*)d_in[3];
    const float* Wq   = (const float*)d_in[4];
    const float* Wk   = (const float*)d_in[5];
    const float* Wv   = (const float*)d_in[6];
    const float* Wo   = (const float*)d_in[7];
    const float* lk   = (const float*)d_in[8];
    const float* lv   = (const float*)d_in[9];
    float* out = (float*)d_out;
    (void)in_sizes; (void)n_in; (void)out_size;

    float *q, *k;
    cudaGetSymbolAddress((void**)&q, g_q);
    cudaGetSymbolAddress((void**)&k, g_k);
    __half *hsH, *wH, *oH, *qh, *kh, *vh;
    cudaGetSymbolAddress((void**)&hsH, g_hs_hi);
    cudaGetSymbolAddress((void**)&wH, g_w_hi);
    cudaGetSymbolAddress((void**)&oH, g_o_hi);
    cudaGetSymbolAddress((void**)&qh, g_qh);
    cudaGetSymbolAddress((void**)&kh, g_kh);
    cudaGetSymbolAddress((void**)&vh, g_vh);

    const int n = S * D;
    conv5_kernel<<<5 * (n / 4) / 256, 256>>>(hs, Wq, Wk, Wv, Wo, hsH, wH, n);

    cudaFuncSetAttribute(gemm_qkv_kernel,
                         cudaFuncAttributeMaxDynamicSharedMemorySize, GSMEM);
    cudaFuncSetAttribute(gemm_out_kernel,
                         cudaFuncAttributeMaxDynamicSharedMemorySize, GSMEM);

    gemm_qkv_kernel<<<dim3(D / 128, S / 128, 3), 256, GSMEM>>>(
        hsH, wH, q, k, vh, lv);

    rope_conv_kernel<<<dim3(S, H), 128>>>(q, k, cosT, sinT, lk, qh, kh);

    int fsmem = QMAT + 2 * 2 * KVMAT;   // 104448
    cudaFuncSetAttribute(flash_mma_kernel,
                         cudaFuncAttributeMaxDynamicSharedMemorySize, fsmem);
    flash_mma_kernel<<<dim3(8, 16), 256, fsmem>>>(qh, kh, vh, oH);

    gemm_out_kernel<<<dim3(D / 128, S / 128), 256, GSMEM>>>(
        oH, wH + 3 * (size_t)n, out);
}

// round 13
// speedup vs baseline: 2.8451x; 1.0930x over previous
#include <cuda_runtime.h>
#include <cuda_fp16.h>
#include <cstdint>
#include <math.h>

#define S 2048
#define D 2048
#define H 16
#define HD 128

// ---- scratch (allocation-free rule: __device__ globals) ----
__device__ __half g_hs_hi[S * D];
__device__ __half g_w_hi[4][D * D];
__device__ __half g_o_hi[S * D];
__device__ __half g_qh[H * S * HD];
__device__ __half g_kh[H * S * HD];
__device__ __half g_vh[H * S * HD];

// ============================================================
// helpers (arch-agnostic: mma.sync / ldmatrix / cp.async)
// ============================================================
__device__ __forceinline__ uint32_t smem_u32(const void* p) {
    uint32_t a;
    asm("{ .reg .u64 t; cvta.to.shared.u64 t, %1; cvt.u32.u64 %0, t; }"
        : "=r"(a) : "l"(p));
    return a;
}
__device__ __forceinline__ void mma16816(float* c, const uint32_t* a,
                                         const uint32_t* b) {
    asm volatile(
        "mma.sync.aligned.m16n8k16.row.col.f32.f16.f16.f32 "
        "{%0,%1,%2,%3}, {%4,%5,%6,%7}, {%8,%9}, {%0,%1,%2,%3};"
        : "+f"(c[0]), "+f"(c[1]), "+f"(c[2]), "+f"(c[3])
        : "r"(a[0]), "r"(a[1]), "r"(a[2]), "r"(a[3]), "r"(b[0]), "r"(b[1]));
}
__device__ __forceinline__ void ldsm4(uint32_t* r, uint32_t addr) {
    asm volatile("ldmatrix.sync.aligned.m8n8.x4.shared.b16 {%0,%1,%2,%3}, [%4];"
                 : "=r"(r[0]), "=r"(r[1]), "=r"(r[2]), "=r"(r[3]) : "r"(addr));
}
__device__ __forceinline__ void ldsm4t(uint32_t* r, uint32_t addr) {
    asm volatile("ldmatrix.sync.aligned.m8n8.x4.trans.shared.b16 {%0,%1,%2,%3}, [%4];"
                 : "=r"(r[0]), "=r"(r[1]), "=r"(r[2]), "=r"(r[3]) : "r"(addr));
}
#define CPASYNC16(sa, ga) \
    asm volatile("cp.async.cg.shared.global [%0], [%1], 16;" \
                 :: "r"(sa), "l"(ga) : "memory")
#define CP_COMMIT() asm volatile("cp.async.commit_group;" ::: "memory")
#define CP_WAIT(N)  asm volatile("cp.async.wait_group %0;" :: "n"(N) : "memory")

// ============================================================
// fused fp32 -> fp16 convert for 5 tensors (hs + 4 weights)
// ============================================================
__global__ __launch_bounds__(256) void conv5_kernel(
    const float* __restrict__ s0, const float* __restrict__ s1,
    const float* __restrict__ s2, const float* __restrict__ s3,
    const float* __restrict__ s4,
    __half* __restrict__ hsH, __half* __restrict__ wH, int n)
{
    int gi = blockIdx.x * 256 + threadIdx.x;
    int per = n / 4;
    int sel = gi / per;
    int i = (gi - sel * per) * 4;
    const float* src = (sel == 0) ? s0 : (sel == 1) ? s1 :
                       (sel == 2) ? s2 : (sel == 3) ? s3 : s4;
    __half* dst = (sel == 0) ? hsH : (wH + (size_t)(sel - 1) * n);
    float4 v = *(const float4*)(src + i);
    ((__half2*)(dst + i))[0] = __floats2half2_rn(v.x, v.y);
    ((__half2*)(dst + i))[1] = __floats2half2_rn(v.z, v.w);
}

// ============================================================
// Fused QKV GEMM + RoPE/IA3 epilogue:
// z=0 -> qh = rope(hs@Wq^T) * lk * scale (fp16)
// z=1 -> kh = rope(hs@Wk^T) (fp16)
// z=2 -> vh = (hs@Wv^T) * lv (fp16)
// n-tile(128) == one head, so rope partners (d, d^64) are in-CTA.
// CTA tile 128x128, K-stage 64, double-buffered.
// ============================================================
#define PITCH 144
#define MATSZ (128 * PITCH)      // 18432
#define STAGESZ (2 * MATSZ)      // 36864
#define GSMEM (2 * STAGESZ)      // 73728
#define FPITCH 132               // fp32 stage pitch (floats)

template <int BODY>
__device__ __forceinline__ void gemm_body(
    const __half* pA, const __half* pB, uint32_t sb,
    int t, int lane, int mw, int nw, float acc[2][8][4])
{
#define LOAD_STAGE(sidx, k0) do {                                            \
        uint32_t base = sb + ((sidx) & 1) * STAGESZ;                         \
        _Pragma("unroll")                                                    \
        for (int mat = 0; mat < 2; mat++) {                                  \
            const __half* g = mat ? pB : pA;                                 \
            _Pragma("unroll")                                                \
            for (int r = 0; r < 4; r++) {                                    \
                int idx = t + 256 * r;                                       \
                int row = idx >> 3, c = idx & 7;                             \
                CPASYNC16(base + mat * MATSZ + row * PITCH + c * 16,         \
                          g + (size_t)row * 2048 + (k0) + c * 8);            \
            }                                                                \
        }                                                                    \
        CP_COMMIT();                                                         \
    } while (0)

    LOAD_STAGE(0, 0);
    for (int s = 0; s < 32; s++) {
        if (s < 31) { LOAD_STAGE(s + 1, (s + 1) * 64); CP_WAIT(1); }
        else        { CP_WAIT(0); }
        __syncthreads();
        const uint32_t base = sb + (s & 1) * STAGESZ;
        const uint32_t aB = base;
        const uint32_t bB = base + MATSZ;
#pragma unroll
        for (int ks = 0; ks < 4; ks++) {
            uint32_t a_hi[2][4], b_hi[8][2];
#pragma unroll
            for (int mt = 0; mt < 2; mt++) {
                int row = mw + mt * 16 + (lane & 15);
                int chunk = 2 * ks + (lane >> 4);
                ldsm4(a_hi[mt], aB + row * PITCH + chunk * 16);
            }
#pragma unroll
            for (int j = 0; j < 4; j++) {
                int row = nw + j * 16 + ((lane >> 4) << 3) + (lane & 7);
                int chunk = 2 * ks + ((lane >> 3) & 1);
                uint32_t rh[4];
                ldsm4(rh, bB + row * PITCH + chunk * 16);
                b_hi[2 * j][0] = rh[0]; b_hi[2 * j][1] = rh[1];
                b_hi[2 * j + 1][0] = rh[2]; b_hi[2 * j + 1][1] = rh[3];
            }
#pragma unroll
            for (int mt = 0; mt < 2; mt++)
#pragma unroll
                for (int nt = 0; nt < 8; nt++)
                    mma16816(acc[mt][nt], a_hi[mt], b_hi[nt]);
        }
        __syncthreads();
    }
#undef LOAD_STAGE
}

__global__ __launch_bounds__(256) void gemm_qkv_kernel(
    const __half* __restrict__ Ahi, const __half* __restrict__ Wall,
    const float* __restrict__ cosT, const float* __restrict__ sinT,
    const float* __restrict__ lk, const float* __restrict__ lv,
    __half* __restrict__ qh, __half* __restrict__ kh,
    __half* __restrict__ Vh)
{
    extern __shared__ char smem[];
    const uint32_t sb = smem_u32(smem);
    const int t = threadIdx.x;
    const int lane = t & 31;
    const int w = t >> 5;
    const int mw = (w >> 1) * 32;
    const int nw = (w & 1) * 64;
    const int mbase = blockIdx.y * 128;
    const int nbase = blockIdx.x * 128;
    const int z = blockIdx.z;

    const __half* pA = Ahi + (size_t)mbase * 2048;
    const __half* pB = Wall + (size_t)z * (2048 * 2048) + (size_t)nbase * 2048;

    float acc[2][8][4];
#pragma unroll
    for (int i = 0; i < 2; i++)
#pragma unroll
        for (int j = 0; j < 8; j++)
#pragma unroll
            for (int k = 0; k < 4; k++) acc[i][j][k] = 0.f;

    gemm_body<0>(pA, pB, sb, t, lane, mw, nw, acc);

    const int hh = nbase >> 7;

    if (z == 2) {
        // V: apply lv, emit fp16 per-head layout
#pragma unroll
        for (int mt = 0; mt < 2; mt++)
#pragma unroll
            for (int nt = 0; nt < 8; nt++) {
                const float* a = acc[mt][nt];
                int r0 = mbase + mw + mt * 16 + (lane >> 2);
                int n  = nbase + nw + nt * 8 + 2 * (lane & 3);
                size_t o0 = ((size_t)hh * 2048 + r0) * 128 + (n & 127);
                size_t o1 = ((size_t)hh * 2048 + r0 + 8) * 128 + (n & 127);
                float s0 = lv[n], s1 = lv[n + 1];
                *(__half2*)&Vh[o0] = __floats2half2_rn(a[0] * s0, a[1] * s1);
                *(__half2*)&Vh[o1] = __floats2half2_rn(a[2] * s0, a[3] * s1);
            }
        return;
    }

    // Q/K: stage fp32 acc tile to smem, then rope in-CTA.
    float* f = (float*)smem;
#pragma unroll
    for (int mt = 0; mt < 2; mt++)
#pragma unroll
        for (int nt = 0; nt < 8; nt++) {
            const float* a = acc[mt][nt];
            int rl = mw + mt * 16 + (lane >> 2);
            int nl = nw + nt * 8 + 2 * (lane & 3);
            f[rl * FPITCH + nl]           = a[0];
            f[rl * FPITCH + nl + 1]       = a[1];
            f[(rl + 8) * FPITCH + nl]     = a[2];
            f[(rl + 8) * FPITCH + nl + 1] = a[3];
        }
    __syncthreads();

    const float scale = 0.08838834764831845f;   // 1/sqrt(128)
#pragma unroll 4
    for (int it = 0; it < 32; it++) {
        int idx = t + 256 * it;       // 0..8191
        int row = idx >> 6;           // 0..127
        int d   = idx & 63;           // 0..63  (partner d+64)
        float x0 = f[row * FPITCH + d];
        float x1 = f[row * FPITCH + d + 64];
        int s = mbase + row;
        float c0 = cosT[s * 128 + d],      sn0 = sinT[s * 128 + d];
        float c1 = cosT[s * 128 + d + 64], sn1 = sinT[s * 128 + d + 64];
        float r0 = x0 * c0 - x1 * sn0;    // d < 64: sign = -1
        float r1 = x1 * c1 + x0 * sn1;    // d >= 64: sign = +1
        size_t rb = ((size_t)hh * 2048 + s) * 128;
        if (z == 0) {
            r0 *= lk[hh * 128 + d] * scale;
            r1 *= lk[hh * 128 + d + 64] * scale;
            qh[rb + d]      = __float2half_rn(r0);
            qh[rb + d + 64] = __float2half_rn(r1);
        } else {
            kh[rb + d]      = __float2half_rn(r0);
            kh[rb + d + 64] = __float2half_rn(r1);
        }
    }
}

__global__ __launch_bounds__(256) void gemm_out_kernel(
    const __half* __restrict__ Ahi, const __half* __restrict__ Bhi,
    float* __restrict__ C)
{
    extern __shared__ char smem[];
    const uint32_t sb = smem_u32(smem);
    const int t = threadIdx.x;
    const int lane = t & 31;
    const int w = t >> 5;
    const int mw = (w >> 1) * 32;
    const int nw = (w & 1) * 64;
    const int mbase = blockIdx.y * 128;
    const int nbase = blockIdx.x * 128;

    const __half* pA = Ahi + (size_t)mbase * 2048;
    const __half* pB = Bhi + (size_t)nbase * 2048;

    float acc[2][8][4];
#pragma unroll
    for (int i = 0; i < 2; i++)
#pragma unroll
        for (int j = 0; j < 8; j++)
#pragma unroll
            for (int k = 0; k < 4; k++) acc[i][j][k] = 0.f;

    gemm_body<1>(pA, pB, sb, t, lane, mw, nw, acc);

#pragma unroll
    for (int mt = 0; mt < 2; mt++)
#pragma unroll
        for (int nt = 0; nt < 8; nt++) {
            const float* a = acc[mt][nt];
            int r0 = mbase + mw + mt * 16 + (lane >> 2);
            int n  = nbase + nw + nt * 8 + 2 * (lane & 3);
            *(float2*)(C + (size_t)r0 * 2048 + n)       = make_float2(a[0], a[1]);
            *(float2*)(C + (size_t)(r0 + 8) * 2048 + n) = make_float2(a[2], a[3]);
        }
}

// ============================================================
// Causal flash attention, mma.sync fp16, triangle-paired.
// Each CTA: q-tiles {15-j, j} (34 kt-iters). Grid 8x16 = 1 wave.
// ============================================================
#define FPB 272
#define QMAT (128 * FPB)
#define KVMAT (64 * FPB)

__global__ __launch_bounds__(256) void flash_mma_kernel(
    const __half* __restrict__ Qh_, const __half* __restrict__ Kh_,
    const __half* __restrict__ Vh_, __half* __restrict__ OH)
{
    extern __shared__ char smem[];
    const uint32_t sb = smem_u32(smem);
    const int t = threadIdx.x, lane = t & 31, w = t >> 5;
    const int j = blockIdx.x;
    const int h = blockIdx.y;
    const int mw = w * 16;
    const size_t hoff = (size_t)h * S * HD;
    const __half* Khp = Kh_ + hoff;
    const __half* Vhp = Vh_ + hoff;

    const uint32_t qB  = sb;
    const uint32_t kvB = sb + QMAT;

#define LOADKV(kt_, p_) do {                                                  \
        uint32_t b_ = kvB + (p_) * (2 * KVMAT);                               \
        const __half* g0 = Khp + (size_t)(kt_) * 64 * 128;                    \
        const __half* g1 = Vhp + (size_t)(kt_) * 64 * 128;                    \
        _Pragma("unroll")                                                     \
        for (int r_ = 0; r_ < 4; r_++) {                                      \
            int idx_ = t + 256 * r_;                                          \
            int row_ = idx_ >> 4, c_ = idx_ & 15;                             \
            uint32_t so_ = row_ * FPB + c_ * 16;                              \
            uint32_t go_ = row_ * 128 + c_ * 8;                               \
            CPASYNC16(b_ + so_,         g0 + go_);                            \
            CPASYNC16(b_ + KVMAT + so_, g1 + go_);                            \
        }                                                                     \
        CP_COMMIT();                                                          \
    } while (0)

    for (int sub = 0; sub < 2; sub++) {
        const int qt = sub ? j : (15 - j);
        const __half* Qhp = Qh_ + hoff + (size_t)qt * 128 * HD;

#pragma unroll
        for (int r = 0; r < 8; r++) {
            int idx = t + 256 * r;
            int row = idx >> 4, c = idx & 15;
            CPASYNC16(qB + row * FPB + c * 16, Qhp + row * 128 + c * 8);
        }
        CP_COMMIT();

        float acc[16][4];
#pragma unroll
        for (int i = 0; i < 16; i++)
#pragma unroll
            for (int jj = 0; jj < 4; jj++) acc[i][jj] = 0.f;
        float m0 = -1e30f, m1 = -1e30f, l0 = 0.f, l1 = 0.f;

        const int ktmax = 2 * qt + 1;
        LOADKV(0, 0);

        for (int kt = 0; kt <= ktmax; kt++) {
            if (kt < ktmax) { LOADKV(kt + 1, (kt + 1) & 1); CP_WAIT(1); }
            else            { CP_WAIT(0); }
            __syncthreads();
            const uint32_t base = kvB + (kt & 1) * (2 * KVMAT);

            float s[8][4];
#pragma unroll
            for (int i = 0; i < 8; i++)
#pragma unroll
                for (int jj = 0; jj < 4; jj++) s[i][jj] = 0.f;
#pragma unroll
            for (int kc = 0; kc < 8; kc++) {
                uint32_t aH[4];
                ldsm4(aH, qB + (mw + (lane & 15)) * FPB + (2 * kc + (lane >> 4)) * 16);
                uint32_t bH[8][2];
#pragma unroll
                for (int jj = 0; jj < 4; jj++) {
                    int row = jj * 16 + ((lane >> 4) << 3) + (lane & 7);
                    uint32_t rh[4];
                    ldsm4(rh, base + row * FPB + (2 * kc + ((lane >> 3) & 1)) * 16);
                    bH[2 * jj][0] = rh[0]; bH[2 * jj][1] = rh[1];
                    bH[2 * jj + 1][0] = rh[2]; bH[2 * jj + 1][1] = rh[3];
                }
#pragma unroll
                for (int nb = 0; nb < 8; nb++)
                    mma16816(s[nb], aH, bH[nb]);
            }

            const int qrow = qt * 128 + mw + (lane >> 2);
            if (kt * 64 + 63 > qt * 128 + mw) {
#pragma unroll
                for (int nb = 0; nb < 8; nb++) {
                    int col = kt * 64 + 8 * nb + 2 * (lane & 3);
                    if (col     > qrow)     s[nb][0] = -1e30f;
                    if (col + 1 > qrow)     s[nb][1] = -1e30f;
                    if (col     > qrow + 8) s[nb][2] = -1e30f;
                    if (col + 1 > qrow + 8) s[nb][3] = -1e30f;
                }
            }

            float mx0 = -1e30f, mx1 = -1e30f;
#pragma unroll
            for (int nb = 0; nb < 8; nb++) {
                mx0 = fmaxf(mx0, fmaxf(s[nb][0], s[nb][1]));
                mx1 = fmaxf(mx1, fmaxf(s[nb][2], s[nb][3]));
            }
            mx0 = fmaxf(mx0, __shfl_xor_sync(0xffffffffu, mx0, 1));
            mx0 = fmaxf(mx0, __shfl_xor_sync(0xffffffffu, mx0, 2));
            mx1 = fmaxf(mx1, __shfl_xor_sync(0xffffffffu, mx1, 1));
            mx1 = fmaxf(mx1, __shfl_xor_sync(0xffffffffu, mx1, 2));
            float mn0 = fmaxf(m0, mx0), mn1 = fmaxf(m1, mx1);
            float al0 = __expf(m0 - mn0), al1 = __expf(m1 - mn1);
            m0 = mn0; m1 = mn1;

            float sum0 = 0.f, sum1 = 0.f;
            uint32_t ph0[8], ph1[8];
#pragma unroll
            for (int nb = 0; nb < 8; nb++) {
                float p0 = __expf(s[nb][0] - mn0), p1 = __expf(s[nb][1] - mn0);
                float p2 = __expf(s[nb][2] - mn1), p3 = __expf(s[nb][3] - mn1);
                sum0 += p0 + p1; sum1 += p2 + p3;
                __half2 h01 = __floats2half2_rn(p0, p1);
                __half2 h23 = __floats2half2_rn(p2, p3);
                ph0[nb] = *(uint32_t*)&h01;
                ph1[nb] = *(uint32_t*)&h23;
            }
            sum0 += __shfl_xor_sync(0xffffffffu, sum0, 1);
            sum0 += __shfl_xor_sync(0xffffffffu, sum0, 2);
            sum1 += __shfl_xor_sync(0xffffffffu, sum1, 1);
            sum1 += __shfl_xor_sync(0xffffffffu, sum1, 2);
            l0 = l0 * al0 + sum0;
            l1 = l1 * al1 + sum1;
#pragma unroll
            for (int nb = 0; nb < 16; nb++) {
                acc[nb][0] *= al0; acc[nb][1] *= al0;
                acc[nb][2] *= al1; acc[nb][3] *= al1;
            }

#pragma unroll
            for (int kc = 0; kc < 4; kc++) {
                uint32_t paH[4] = {ph0[2 * kc], ph1[2 * kc],
                                   ph0[2 * kc + 1], ph1[2 * kc + 1]};
#pragma unroll
                for (int nb2 = 0; nb2 < 8; nb2++) {
                    uint32_t vaddr = base + KVMAT +
                                     (kc * 16 + (lane & 15)) * FPB +
                                     (2 * nb2 + (lane >> 4)) * 16;
                    uint32_t vh[4];
                    ldsm4t(vh, vaddr);
                    uint32_t bh0[2] = {vh[0], vh[1]}, bh1[2] = {vh[2], vh[3]};
                    mma16816(acc[2 * nb2], paH, bh0);
                    mma16816(acc[2 * nb2 + 1], paH, bh1);
                }
            }
            __syncthreads();
        }

        float inv0 = 1.f / l0, inv1 = 1.f / l1;
        int r = qt * 128 + mw + (lane >> 2);
#pragma unroll
        for (int nb = 0; nb < 16; nb++) {
            int col = h * 128 + 8 * nb + 2 * (lane & 3);
            *(__half2*)&OH[(size_t)r * D + col] =
                __floats2half2_rn(acc[nb][0] * inv0, acc[nb][1] * inv0);
            *(__half2*)&OH[(size_t)(r + 8) * D + col] =
                __floats2half2_rn(acc[nb][2] * inv1, acc[nb][3] * inv1);
        }
    }
}

// ============================================================
extern "C" void kernel_launch(void* const* d_in, const int* in_sizes, int n_in,
                              void* d_out, int out_size)
{
    const float* hs   = (const float*)d_in[0];
    const float* cosT = (const float*)d_in[2];
    const float* sinT = (const float*)d_in[3];
    const float* Wq   = (const float*)d_in[4];
    const float* Wk   = (const float*)d_in[5];
    const float* Wv   = (const float*)d_in[6];
    const float* Wo   = (const float*)d_in[7];
    const float* lk   = (const float*)d_in[8];
    const float* lv   = (const float*)d_in[9];
    float* out = (float*)d_out;
    (void)in_sizes; (void)n_in; (void)out_size;

    __half *hsH, *wH, *oH, *qh, *kh, *vh;
    cudaGetSymbolAddress((void**)&hsH, g_hs_hi);
    cudaGetSymbolAddress((void**)&wH, g_w_hi);
    cudaGetSymbolAddress((void**)&oH, g_o_hi);
    cudaGetSymbolAddress((void**)&qh, g_qh);
    cudaGetSymbolAddress((void**)&kh, g_kh);
    cudaGetSymbolAddress((void**)&vh, g_vh);

    const int n = S * D;
    conv5_kernel<<<5 * (n / 4) / 256, 256>>>(hs, Wq, Wk, Wv, Wo, hsH, wH, n);

    cudaFuncSetAttribute(gemm_qkv_kernel,
                         cudaFuncAttributeMaxDynamicSharedMemorySize, GSMEM);
    cudaFuncSetAttribute(gemm_out_kernel,
                         cudaFuncAttributeMaxDynamicSharedMemorySize, GSMEM);

    gemm_qkv_kernel<<<dim3(D / 128, S / 128, 3), 256, GSMEM>>>(
        hsH, wH, cosT, sinT, lk, lv, qh, kh, vh);

    int fsmem = QMAT + 2 * 2 * KVMAT;   // 104448
    cudaFuncSetAttribute(flash_mma_kernel,
                         cudaFuncAttributeMaxDynamicSharedMemorySize, fsmem);
    flash_mma_kernel<<<dim3(8, 16), 256, fsmem>>>(qh, kh, vh, oH);

    gemm_out_kernel<<<dim3(D / 128, S / 128), 256, GSMEM>>>(
        oH, wH + 3 * (size_t)n, out);
}